// round 1
// baseline (speedup 1.0000x reference)
#include <cuda_runtime.h>
#include <math.h>

// ---------------- problem constants (fixed by setup_inputs) ----------------
constexpr int B   = 8;
constexpr int F   = 8;          // frames
constexpr int NS  = 196;        // spatial tokens per frame
constexpr int NT  = 1 + F*NS;   // 1569 tokens
constexpr int D   = 768;
constexpr int H   = 12;
constexpr int HD  = 64;
constexpr int D3  = 3*D;        // 2304
constexpr int D4  = 4*D;        // 3072
constexpr int M   = B*NT;       // 12552 rows
constexpr float LN_EPS = 1e-5f;
constexpr float QSCALE = 0.125f; // hd^-0.5

// ---------------- scratch (static device globals; no allocation) -----------
__device__ float g_ln  [(size_t)M * D];
__device__ float g_qkv [(size_t)M * D3];
__device__ float g_att [(size_t)M * D];
__device__ float g_tres[(size_t)M * D];
__device__ float g_sres[(size_t)M * D];
__device__ float g_hid [(size_t)M * D4];

// ---------------- LayerNorm ------------------------------------------------
__global__ void ln_kernel(const float* __restrict__ X,
                          const float* __restrict__ gam,
                          const float* __restrict__ bet,
                          float* __restrict__ Y)
{
    int row = blockIdx.x;
    const float* x = X + (size_t)row * D;
    float* y = Y + (size_t)row * D;
    int tid = threadIdx.x;

    float s = 0.f, ss = 0.f;
    for (int i = tid; i < D; i += 256) { float v = x[i]; s += v; ss += v*v; }

    __shared__ float rs[32], rss[32];
    // warp reduce
    for (int o = 16; o > 0; o >>= 1) {
        s  += __shfl_xor_sync(0xffffffffu, s,  o);
        ss += __shfl_xor_sync(0xffffffffu, ss, o);
    }
    int wid = tid >> 5, lid = tid & 31;
    if (lid == 0) { rs[wid] = s; rss[wid] = ss; }
    __syncthreads();
    __shared__ float s_mean, s_inv;
    if (tid == 0) {
        float ts = 0.f, tss = 0.f;
        for (int w = 0; w < 8; w++) { ts += rs[w]; tss += rss[w]; }
        float mean = ts * (1.f/D);
        float var  = tss * (1.f/D) - mean*mean;
        s_mean = mean;
        s_inv  = rsqrtf(var + LN_EPS);
    }
    __syncthreads();
    float mean = s_mean, inv = s_inv;
    for (int i = tid; i < D; i += 256)
        y[i] = (x[i] - mean) * inv * gam[i] + bet[i];
}

// ---------------- SGEMM: C = A(MxK) @ W(KxN) + bias [+R | gelu] -----------
// EPI: 0 = bias only, 1 = bias + residual, 2 = bias + exact GELU
__device__ __forceinline__ float gelu_exact(float v) {
    return 0.5f * v * (1.f + erff(v * 0.70710678118654752f));
}

template<int EPI>
__global__ void sgemm_kernel(const float* __restrict__ A,
                             const float* __restrict__ W,
                             const float* __restrict__ bias,
                             const float* __restrict__ R,
                             float* __restrict__ C,
                             int Mr, int K, int Nc)
{
    __shared__ float As[16][64];
    __shared__ float Bs[16][64];

    int tid = threadIdx.x;              // 256
    int bm = blockIdx.y * 64;
    int bn = blockIdx.x * 64;
    int tx = tid & 15, ty = tid >> 4;

    // load mapping
    int am  = tid >> 2;                 // 0..63
    int ak  = (tid & 3) * 4;            // 0,4,8,12
    int bk  = tid >> 4;                 // 0..15
    int bn4 = (tid & 15) * 4;           // 0..60

    float acc[4][4];
    #pragma unroll
    for (int i = 0; i < 4; i++)
        #pragma unroll
        for (int j = 0; j < 4; j++) acc[i][j] = 0.f;

    for (int k0 = 0; k0 < K; k0 += 16) {
        float4 av;
        int arow = bm + am;
        if (arow < Mr) av = *(const float4*)&A[(size_t)arow * K + k0 + ak];
        else           av = make_float4(0.f,0.f,0.f,0.f);
        As[ak+0][am] = av.x; As[ak+1][am] = av.y;
        As[ak+2][am] = av.z; As[ak+3][am] = av.w;

        float4 bv = *(const float4*)&W[(size_t)(k0 + bk) * Nc + bn + bn4];
        *(float4*)&Bs[bk][bn4] = bv;
        __syncthreads();

        #pragma unroll
        for (int kk = 0; kk < 16; kk++) {
            float4 ra = *(const float4*)&As[kk][ty*4];
            float4 rb = *(const float4*)&Bs[kk][tx*4];
            float a0=ra.x, a1=ra.y, a2=ra.z, a3=ra.w;
            float b0=rb.x, b1=rb.y, b2=rb.z, b3=rb.w;
            acc[0][0]+=a0*b0; acc[0][1]+=a0*b1; acc[0][2]+=a0*b2; acc[0][3]+=a0*b3;
            acc[1][0]+=a1*b0; acc[1][1]+=a1*b1; acc[1][2]+=a1*b2; acc[1][3]+=a1*b3;
            acc[2][0]+=a2*b0; acc[2][1]+=a2*b1; acc[2][2]+=a2*b2; acc[2][3]+=a2*b3;
            acc[3][0]+=a3*b0; acc[3][1]+=a3*b1; acc[3][2]+=a3*b2; acc[3][3]+=a3*b3;
        }
        __syncthreads();
    }

    #pragma unroll
    for (int i = 0; i < 4; i++) {
        int m = bm + ty*4 + i;
        if (m >= Mr) continue;
        #pragma unroll
        for (int j = 0; j < 4; j++) {
            int nn = bn + tx*4 + j;
            float v = acc[i][j] + bias[nn];
            if (EPI == 1) v += R[(size_t)m * Nc + nn];
            if (EPI == 2) v = gelu_exact(v);
            C[(size_t)m * Nc + nn] = v;
        }
    }
}

// ---------------- cls-token attention (full sequence) ----------------------
__global__ void attn_cls_kernel(const float* __restrict__ qkv,
                                float* __restrict__ att)
{
    int bh = blockIdx.x;
    int b = bh / H, hh = bh % H;
    int tid = threadIdx.x;

    __shared__ float qs[HD];
    __shared__ float sim[NT];
    __shared__ float red[256];
    __shared__ float red2[4][HD];

    if (tid < HD)
        qs[tid] = qkv[(size_t)(b*NT) * D3 + hh*HD + tid] * QSCALE;
    __syncthreads();

    float lmx = -1e30f;
    for (int j = tid; j < NT; j += 256) {
        const float* kp = qkv + (size_t)(b*NT + j) * D3 + D + hh*HD;
        float s = 0.f;
        #pragma unroll
        for (int d = 0; d < HD; d++) s += qs[d] * kp[d];
        sim[j] = s;
        lmx = fmaxf(lmx, s);
    }
    red[tid] = lmx; __syncthreads();
    for (int st = 128; st > 0; st >>= 1) {
        if (tid < st) red[tid] = fmaxf(red[tid], red[tid+st]);
        __syncthreads();
    }
    float mx = red[0];
    __syncthreads();

    float ls = 0.f;
    for (int j = tid; j < NT; j += 256) {
        float e = __expf(sim[j] - mx);
        sim[j] = e;
        ls += e;
    }
    red[tid] = ls; __syncthreads();
    for (int st = 128; st > 0; st >>= 1) {
        if (tid < st) red[tid] += red[tid+st];
        __syncthreads();
    }
    float linv = 1.f / red[0];
    __syncthreads();

    int d = tid & 63, p = tid >> 6;   // p in 0..3
    float acc = 0.f;
    for (int j = p; j < NT; j += 4)
        acc += sim[j] * qkv[(size_t)(b*NT + j) * D3 + 2*D + hh*HD + d];
    red2[p][d] = acc;
    __syncthreads();
    if (p == 0) {
        float o = (red2[0][d] + red2[1][d] + red2[2][d] + red2[3][d]) * linv;
        att[(size_t)(b*NT) * D + hh*HD + d] = o;
    }
}

// ---------------- time attention: groups (bh, sp), 8 q x 9 keys ------------
__global__ void attn_time_kernel(const float* __restrict__ qkv,
                                 float* __restrict__ att)
{
    int qid = blockIdx.x * blockDim.x + threadIdx.x;   // < 96*196*8
    int fr = qid % F;
    int sp = (qid / F) % NS;
    int bh = qid / (F * NS);
    int b = bh / H, hh = bh % H;
    int t = 1 + fr*NS + sp;

    const float4* qp = (const float4*)(qkv + (size_t)(b*NT + t) * D3 + hh*HD);
    float4 q4[16];
    #pragma unroll
    for (int i = 0; i < 16; i++) {
        float4 v = qp[i];
        v.x *= QSCALE; v.y *= QSCALE; v.z *= QSCALE; v.w *= QSCALE;
        q4[i] = v;
    }

    float sim[F+1];
    #pragma unroll
    for (int j = 0; j < F+1; j++) {
        int tk = (j == 0) ? 0 : (1 + (j-1)*NS + sp);
        const float4* kp = (const float4*)(qkv + (size_t)(b*NT + tk) * D3 + D + hh*HD);
        float s = 0.f;
        #pragma unroll
        for (int i = 0; i < 16; i++) {
            float4 kk = kp[i];
            s += q4[i].x*kk.x + q4[i].y*kk.y + q4[i].z*kk.z + q4[i].w*kk.w;
        }
        sim[j] = s;
    }
    float mx = sim[0];
    #pragma unroll
    for (int j = 1; j < F+1; j++) mx = fmaxf(mx, sim[j]);
    float l = 0.f;
    #pragma unroll
    for (int j = 0; j < F+1; j++) { sim[j] = __expf(sim[j] - mx); l += sim[j]; }
    float inv = 1.f / l;

    float4 o4[16];
    #pragma unroll
    for (int i = 0; i < 16; i++) o4[i] = make_float4(0.f,0.f,0.f,0.f);
    #pragma unroll
    for (int j = 0; j < F+1; j++) {
        int tk = (j == 0) ? 0 : (1 + (j-1)*NS + sp);
        const float4* vp = (const float4*)(qkv + (size_t)(b*NT + tk) * D3 + 2*D + hh*HD);
        float p = sim[j] * inv;
        #pragma unroll
        for (int i = 0; i < 16; i++) {
            float4 vv = vp[i];
            o4[i].x += p*vv.x; o4[i].y += p*vv.y; o4[i].z += p*vv.z; o4[i].w += p*vv.w;
        }
    }
    float4* op = (float4*)(att + (size_t)(b*NT + t) * D + hh*HD);
    #pragma unroll
    for (int i = 0; i < 16; i++) op[i] = o4[i];
}

// ---------------- space attention: groups (bh, fr), 196 q x 197 keys -------
__global__ void attn_space_kernel(const float* __restrict__ qkv,
                                  float* __restrict__ att)
{
    int bx = blockIdx.x;            // bh*F + fr
    int bh = bx / F, fr = bx % F;
    int b = bh / H, hh = bh % H;
    int tid = threadIdx.x;          // 256
    int sp = tid;                   // active if < NS
    const int NK = NS + 1;          // 197 keys

    __shared__ float Ks[64 * HD];
    __shared__ float Vs[64 * HD];

    float4 q4[16], o4[16];
    float m = -1e30f, l = 0.f;
    if (sp < NS) {
        const float4* qp = (const float4*)(qkv + (size_t)(b*NT + 1 + fr*NS + sp) * D3 + hh*HD);
        #pragma unroll
        for (int i = 0; i < 16; i++) {
            float4 v = qp[i];
            v.x *= QSCALE; v.y *= QSCALE; v.z *= QSCALE; v.w *= QSCALE;
            q4[i] = v;
            o4[i] = make_float4(0.f,0.f,0.f,0.f);
        }
    }

    for (int t0 = 0; t0 < NK; t0 += 64) {
        __syncthreads();
        for (int e = tid; e < 64*HD; e += 256) {
            int jj = e >> 6, d = e & 63;
            int j = t0 + jj;
            float kv = 0.f, vv = 0.f;
            if (j < NK) {
                int tk = (j == 0) ? 0 : (1 + fr*NS + (j-1));
                size_t base = (size_t)(b*NT + tk) * D3 + hh*HD + d;
                kv = qkv[base + D];
                vv = qkv[base + 2*D];
            }
            Ks[e] = kv; Vs[e] = vv;
        }
        __syncthreads();

        if (sp < NS) {
            int lim = min(64, NK - t0);
            for (int jj = 0; jj < lim; jj++) {
                const float4* kr = (const float4*)&Ks[jj * HD];
                float s = 0.f;
                #pragma unroll
                for (int i = 0; i < 16; i++) {
                    float4 kk = kr[i];
                    s += q4[i].x*kk.x + q4[i].y*kk.y + q4[i].z*kk.z + q4[i].w*kk.w;
                }
                float mn  = fmaxf(m, s);
                float fac = __expf(m - mn);
                float p   = __expf(s - mn);
                l = l * fac + p;
                const float4* vr = (const float4*)&Vs[jj * HD];
                #pragma unroll
                for (int i = 0; i < 16; i++) {
                    float4 vv = vr[i];
                    o4[i].x = o4[i].x*fac + p*vv.x;
                    o4[i].y = o4[i].y*fac + p*vv.y;
                    o4[i].z = o4[i].z*fac + p*vv.z;
                    o4[i].w = o4[i].w*fac + p*vv.w;
                }
                m = mn;
            }
        }
    }

    if (sp < NS) {
        float inv = 1.f / l;
        float4* op = (float4*)(att + (size_t)(b*NT + 1 + fr*NS + sp) * D + hh*HD);
        #pragma unroll
        for (int i = 0; i < 16; i++)
            op[i] = make_float4(o4[i].x*inv, o4[i].y*inv, o4[i].z*inv, o4[i].w*inv);
    }
}

// ---------------- host launch ----------------------------------------------
extern "C" void kernel_launch(void* const* d_in, const int* in_sizes, int n_in,
                              void* d_out, int out_size)
{
    const float* x      = (const float*)d_in[0];
    const float* n1g    = (const float*)d_in[1];
    const float* n1b    = (const float*)d_in[2];
    const float* n2g    = (const float*)d_in[3];
    const float* n2b    = (const float*)d_in[4];
    const float* n3g    = (const float*)d_in[5];
    const float* n3b    = (const float*)d_in[6];
    const float* aqkvw  = (const float*)d_in[7];
    const float* aqkvb  = (const float*)d_in[8];
    const float* aprojw = (const float*)d_in[9];
    const float* aprojb = (const float*)d_in[10];
    const float* tqkvw  = (const float*)d_in[11];
    const float* tqkvb  = (const float*)d_in[12];
    const float* tprojw = (const float*)d_in[13];
    const float* tprojb = (const float*)d_in[14];
    const float* fc1w   = (const float*)d_in[15];
    const float* fc1b   = (const float*)d_in[16];
    const float* fc2w   = (const float*)d_in[17];
    const float* fc2b   = (const float*)d_in[18];
    float* out = (float*)d_out;

    static float *bln=nullptr,*bqkv=nullptr,*batt=nullptr,*btres=nullptr,*bsres=nullptr,*bhid=nullptr;
    if (!bln) {
        cudaGetSymbolAddress((void**)&bln,  g_ln);
        cudaGetSymbolAddress((void**)&bqkv, g_qkv);
        cudaGetSymbolAddress((void**)&batt, g_att);
        cudaGetSymbolAddress((void**)&btres,g_tres);
        cudaGetSymbolAddress((void**)&bsres,g_sres);
        cudaGetSymbolAddress((void**)&bhid, g_hid);
    }

    const int MB = (M + 63) / 64;           // 197
    dim3 g_qkvd(D3/64, MB), g_d(D/64, MB), g_h(D4/64, MB);
    const int nTimeBlocks = (B*H*NS*F) / 256;  // 588

    // ---- time attention branch ----
    ln_kernel<<<M, 256>>>(x, n3g, n3b, bln);
    sgemm_kernel<0><<<g_qkvd, 256>>>(bln, tqkvw, tqkvb, nullptr, bqkv, M, D, D3);
    attn_cls_kernel <<<B*H, 256>>>(bqkv, batt);
    attn_time_kernel<<<nTimeBlocks, 256>>>(bqkv, batt);
    sgemm_kernel<1><<<g_d, 256>>>(batt, tprojw, tprojb, x, btres, M, D, D);

    // ---- space attention branch ----
    ln_kernel<<<M, 256>>>(btres, n1g, n1b, bln);
    sgemm_kernel<0><<<g_qkvd, 256>>>(bln, aqkvw, aqkvb, nullptr, bqkv, M, D, D3);
    attn_cls_kernel  <<<B*H, 256>>>(bqkv, batt);
    attn_space_kernel<<<B*H*F, 256>>>(bqkv, batt);
    sgemm_kernel<1><<<g_d, 256>>>(batt, aprojw, aprojb, x, bsres, M, D, D);

    // ---- MLP ----
    ln_kernel<<<M, 256>>>(bsres, n2g, n2b, bln);
    sgemm_kernel<2><<<g_h, 256>>>(bln, fc1w, fc1b, nullptr, bhid, M, D, D4);
    sgemm_kernel<1><<<g_d, 256>>>(bhid, fc2w, fc2b, bsres, out, M, D4, D);
}

// round 3
// speedup vs baseline: 2.2509x; 2.2509x over previous
#include <cuda_runtime.h>
#include <cuda_bf16.h>
#include <math.h>
#include <cstdint>

// ---------------- problem constants ----------------------------------------
constexpr int B   = 8;
constexpr int F   = 8;
constexpr int NS  = 196;
constexpr int NT  = 1 + F*NS;   // 1569
constexpr int D   = 768;
constexpr int H   = 12;
constexpr int HD  = 64;
constexpr int D3  = 3*D;        // 2304
constexpr int D4  = 4*D;        // 3072
constexpr int M   = B*NT;       // 12552
constexpr float LN_EPS = 1e-5f;
constexpr float QSCALE = 0.125f;

// ---------------- scratch (device globals; no allocation) ------------------
__device__ __nv_bfloat16 g_lnh [(size_t)M * D];
__device__ __nv_bfloat16 g_lnl [(size_t)M * D];
__device__ float         g_qkv [(size_t)M * D3];
__device__ float         g_att [(size_t)M * D];
__device__ __nv_bfloat16 g_atth[(size_t)M * D];
__device__ __nv_bfloat16 g_attl[(size_t)M * D];
__device__ float         g_tres[(size_t)M * D];
__device__ float         g_sres[(size_t)M * D];
__device__ float         g_hid [(size_t)M * D4];
__device__ __nv_bfloat16 g_hidh[(size_t)M * D4];
__device__ __nv_bfloat16 g_hidl[(size_t)M * D4];
// transposed+split weights: Wt[n][k] = W[k][n]
__device__ __nv_bfloat16 g_wth_tqkv [(size_t)D3*D], g_wtl_tqkv [(size_t)D3*D];
__device__ __nv_bfloat16 g_wth_aqkv [(size_t)D3*D], g_wtl_aqkv [(size_t)D3*D];
__device__ __nv_bfloat16 g_wth_tproj[(size_t)D*D],  g_wtl_tproj[(size_t)D*D];
__device__ __nv_bfloat16 g_wth_aproj[(size_t)D*D],  g_wtl_aproj[(size_t)D*D];
__device__ __nv_bfloat16 g_wth_fc1  [(size_t)D4*D], g_wtl_fc1  [(size_t)D4*D];
__device__ __nv_bfloat16 g_wth_fc2  [(size_t)D*D4], g_wtl_fc2  [(size_t)D*D4];

// ---------------- helpers ----------------------------------------------------
__device__ __forceinline__ uint32_t smem_to_u32(const void* p) {
    uint32_t a;
    asm("{ .reg .u64 t; cvta.to.shared.u64 t, %1; cvt.u32.u64 %0, t; }"
        : "=r"(a) : "l"(p));
    return a;
}

__device__ __forceinline__ void cp_async16(uint32_t dst, const void* src, bool valid) {
    int sz = valid ? 16 : 0;
    asm volatile("cp.async.cg.shared.global [%0], [%1], 16, %2;"
                 :: "r"(dst), "l"(src), "r"(sz) : "memory");
}
#define CP_COMMIT()  asm volatile("cp.async.commit_group;" ::: "memory")
#define CP_WAIT(n)   asm volatile("cp.async.wait_group %0;" :: "n"(n) : "memory")

__device__ __forceinline__ void ldsm_x4(uint32_t& r0, uint32_t& r1, uint32_t& r2, uint32_t& r3, uint32_t addr) {
    asm volatile("ldmatrix.sync.aligned.m8n8.x4.shared.b16 {%0,%1,%2,%3}, [%4];"
                 : "=r"(r0), "=r"(r1), "=r"(r2), "=r"(r3) : "r"(addr));
}
__device__ __forceinline__ void ldsm_x2(uint32_t& r0, uint32_t& r1, uint32_t addr) {
    asm volatile("ldmatrix.sync.aligned.m8n8.x2.shared.b16 {%0,%1}, [%2];"
                 : "=r"(r0), "=r"(r1) : "r"(addr));
}
__device__ __forceinline__ void mma16816(float* c, const uint32_t* a, const uint32_t* b) {
    asm volatile(
        "mma.sync.aligned.m16n8k16.row.col.f32.bf16.bf16.f32 "
        "{%0,%1,%2,%3}, {%4,%5,%6,%7}, {%8,%9}, {%0,%1,%2,%3};"
        : "+f"(c[0]), "+f"(c[1]), "+f"(c[2]), "+f"(c[3])
        : "r"(a[0]), "r"(a[1]), "r"(a[2]), "r"(a[3]), "r"(b[0]), "r"(b[1]));
}

__device__ __forceinline__ float gelu_exact(float v) {
    return 0.5f * v * (1.f + erff(v * 0.70710678118654752f));
}

// ---------------- GEMM (mma.sync bf16x3 split) -------------------------------
// C[M][N] = A[M][K] @ Wt[N][K]^T with A,Wt given as hi/lo bf16 pairs.
// CTA: 128x128 tile, K-chunk 32, 256 threads = 8 warps (2 x 4 of 64x32).
constexpr int BM = 128, BN = 128, BK = 32;
constexpr int RSB = 80;                // padded row stride in bytes (40 bf16)
constexpr int MAT_B = 128 * RSB;       // 10240 B per matrix tile
constexpr int STAGE_B = 4 * MAT_B;     // Ah, Al, Bh, Bl
constexpr int SMEM_GEMM = 2 * STAGE_B; // 81920 B

// EPI: 0 = bias, 1 = bias+residual, 2 = bias+GELU
template<int EPI>
__global__ void __launch_bounds__(256, 1)
gemm_bf16x3(const __nv_bfloat16* __restrict__ Ah, const __nv_bfloat16* __restrict__ Al,
            const __nv_bfloat16* __restrict__ Bh, const __nv_bfloat16* __restrict__ Bl,
            const float* __restrict__ bias, const float* __restrict__ R,
            float* __restrict__ C, int Mr, int K, int Nc)
{
    extern __shared__ char smem[];
    const uint32_t sb = smem_to_u32(smem);
    const int tid = threadIdx.x;
    const int wid = tid >> 5, lane = tid & 31;
    const int wm = wid & 1, wn = wid >> 1;          // warp tile: (wm*64, wn*32)
    const int bm = blockIdx.y * BM, bn = blockIdx.x * BN;

    float acc[4][4][4];
    #pragma unroll
    for (int i = 0; i < 4; i++)
        #pragma unroll
        for (int j = 0; j < 4; j++)
            #pragma unroll
            for (int q = 0; q < 4; q++) acc[i][j][q] = 0.f;

    // global->smem load of one stage (Ah/Al rows from A matrices, Bh/Bl rows from W)
    auto load_stage = [&](int stage, int k0) {
        uint32_t base = sb + stage * STAGE_B;
        // A: 128 rows x 32 bf16 (64B) = 512 chunks of 16B; 2 per thread per matrix
        #pragma unroll
        for (int i = 0; i < 2; i++) {
            int idx = tid + i*256;
            int r = idx >> 2, cb = (idx & 3) << 4;   // row, byte-in-row
            int gr = bm + r;
            bool v = gr < Mr;
            const char* srcH = (const char*)(Ah + (size_t)(v ? gr : 0) * K + k0) + cb;
            const char* srcL = (const char*)(Al + (size_t)(v ? gr : 0) * K + k0) + cb;
            cp_async16(base + 0*MAT_B + r*RSB + cb, srcH, v);
            cp_async16(base + 1*MAT_B + r*RSB + cb, srcL, v);
        }
        // B: 128 rows (n) x 32 bf16; N is always a multiple of 128 -> no guard
        #pragma unroll
        for (int i = 0; i < 2; i++) {
            int idx = tid + i*256;
            int r = idx >> 2, cb = (idx & 3) << 4;
            const char* srcH = (const char*)(Bh + (size_t)(bn + r) * K + k0) + cb;
            const char* srcL = (const char*)(Bl + (size_t)(bn + r) * K + k0) + cb;
            cp_async16(base + 2*MAT_B + r*RSB + cb, srcH, true);
            cp_async16(base + 3*MAT_B + r*RSB + cb, srcL, true);
        }
        CP_COMMIT();
    };

    const int NC = K / BK;
    load_stage(0, 0);

    // ldmatrix lane addressing
    const int aRow = (lane & 15);            // + tile base
    const int aColB = (lane >> 4) * 16;      // byte offset (8 bf16)
    const int bRow = (lane & 7);
    const int bColB = ((lane >> 3) & 1) * 16;

    for (int c = 0; c < NC; c++) {
        if (c + 1 < NC) load_stage((c + 1) & 1, (c + 1) * BK);
        if (c + 1 < NC) { CP_WAIT(1); } else { CP_WAIT(0); }
        __syncthreads();

        uint32_t st = sb + (c & 1) * STAGE_B;
        uint32_t aHb = st + 0*MAT_B, aLb = st + 1*MAT_B;
        uint32_t bHb = st + 2*MAT_B, bLb = st + 3*MAT_B;

        #pragma unroll
        for (int kk = 0; kk < 2; kk++) {
            uint32_t ah[4][4], al[4][4], bh[4][2], bl[4][2];
            #pragma unroll
            for (int mt = 0; mt < 4; mt++) {
                uint32_t off = (uint32_t)((wm*64 + mt*16 + aRow) * RSB + kk*32 + aColB);
                ldsm_x4(ah[mt][0], ah[mt][1], ah[mt][2], ah[mt][3], aHb + off);
                ldsm_x4(al[mt][0], al[mt][1], al[mt][2], al[mt][3], aLb + off);
            }
            #pragma unroll
            for (int nt = 0; nt < 4; nt++) {
                uint32_t off = (uint32_t)((wn*32 + nt*8 + bRow) * RSB + kk*32 + bColB);
                ldsm_x2(bh[nt][0], bh[nt][1], bHb + off);
                ldsm_x2(bl[nt][0], bl[nt][1], bLb + off);
            }
            #pragma unroll
            for (int mt = 0; mt < 4; mt++) {
                #pragma unroll
                for (int nt = 0; nt < 4; nt++) {
                    mma16816(acc[mt][nt], ah[mt], bh[nt]);
                    mma16816(acc[mt][nt], ah[mt], bl[nt]);
                    mma16816(acc[mt][nt], al[mt], bh[nt]);
                }
            }
        }
        __syncthreads();
    }

    // epilogue: thread owns rows (lane>>2, +8), cols 2*(lane&3) within each 16x8 tile
    const int er = lane >> 2, ec = (lane & 3) * 2;
    #pragma unroll
    for (int mt = 0; mt < 4; mt++) {
        int r0 = bm + wm*64 + mt*16 + er;
        int r1 = r0 + 8;
        #pragma unroll
        for (int nt = 0; nt < 4; nt++) {
            int cc = bn + wn*32 + nt*8 + ec;
            float b0 = bias[cc], b1 = bias[cc + 1];
            if (r0 < Mr) {
                float v0 = acc[mt][nt][0] + b0;
                float v1 = acc[mt][nt][1] + b1;
                size_t off = (size_t)r0 * Nc + cc;
                if (EPI == 1) { v0 += R[off]; v1 += R[off + 1]; }
                if (EPI == 2) { v0 = gelu_exact(v0); v1 = gelu_exact(v1); }
                C[off] = v0; C[off + 1] = v1;
            }
            if (r1 < Mr) {
                float v2 = acc[mt][nt][2] + b0;
                float v3 = acc[mt][nt][3] + b1;
                size_t off = (size_t)r1 * Nc + cc;
                if (EPI == 1) { v2 += R[off]; v3 += R[off + 1]; }
                if (EPI == 2) { v2 = gelu_exact(v2); v3 = gelu_exact(v3); }
                C[off] = v2; C[off + 1] = v3;
            }
        }
    }
}

// ---------------- LayerNorm with bf16 hi/lo split output --------------------
__global__ void ln_split_kernel(const float* __restrict__ X,
                                const float* __restrict__ gam,
                                const float* __restrict__ bet,
                                __nv_bfloat16* __restrict__ Hi,
                                __nv_bfloat16* __restrict__ Lo)
{
    int row = blockIdx.x;
    const float* x = X + (size_t)row * D;
    int tid = threadIdx.x;

    float s = 0.f, ss = 0.f;
    for (int i = tid; i < D; i += 256) { float v = x[i]; s += v; ss += v*v; }
    __shared__ float rs[32], rss[32];
    for (int o = 16; o > 0; o >>= 1) {
        s  += __shfl_xor_sync(0xffffffffu, s,  o);
        ss += __shfl_xor_sync(0xffffffffu, ss, o);
    }
    int wid = tid >> 5, lid = tid & 31;
    if (lid == 0) { rs[wid] = s; rss[wid] = ss; }
    __syncthreads();
    __shared__ float s_mean, s_inv;
    if (tid == 0) {
        float ts = 0.f, tss = 0.f;
        for (int w = 0; w < 8; w++) { ts += rs[w]; tss += rss[w]; }
        float mean = ts * (1.f/D);
        float var  = tss * (1.f/D) - mean*mean;
        s_mean = mean; s_inv = rsqrtf(var + LN_EPS);
    }
    __syncthreads();
    float mean = s_mean, inv = s_inv;
    for (int i = tid; i < D; i += 256) {
        float v = (x[i] - mean) * inv * gam[i] + bet[i];
        __nv_bfloat16 h = __float2bfloat16(v);
        Hi[(size_t)row*D + i] = h;
        Lo[(size_t)row*D + i] = __float2bfloat16(v - __bfloat162float(h));
    }
}

// ---------------- fp32 -> bf16 hi/lo split ----------------------------------
__global__ void split_kernel(const float4* __restrict__ X,
                             __nv_bfloat162* __restrict__ Hi,
                             __nv_bfloat162* __restrict__ Lo, int n4)
{
    int i = blockIdx.x * blockDim.x + threadIdx.x;
    if (i >= n4) return;
    float4 v = X[i];
    __nv_bfloat16 h0 = __float2bfloat16(v.x), h1 = __float2bfloat16(v.y);
    __nv_bfloat16 h2 = __float2bfloat16(v.z), h3 = __float2bfloat16(v.w);
    __nv_bfloat16 l0 = __float2bfloat16(v.x - __bfloat162float(h0));
    __nv_bfloat16 l1 = __float2bfloat16(v.y - __bfloat162float(h1));
    __nv_bfloat16 l2 = __float2bfloat16(v.z - __bfloat162float(h2));
    __nv_bfloat16 l3 = __float2bfloat16(v.w - __bfloat162float(h3));
    Hi[2*i]   = __halves2bfloat162(h0, h1);
    Hi[2*i+1] = __halves2bfloat162(h2, h3);
    Lo[2*i]   = __halves2bfloat162(l0, l1);
    Lo[2*i+1] = __halves2bfloat162(l2, l3);
}

// ---------------- transpose + split: W[K][N] -> Th/Tl[N][K] ------------------
__global__ void tsplit_kernel(const float* __restrict__ W,
                              __nv_bfloat16* __restrict__ Th,
                              __nv_bfloat16* __restrict__ Tl, int K, int N)
{
    __shared__ float t[32][33];
    int n0 = blockIdx.x * 32, k0 = blockIdx.y * 32;
    int tx = threadIdx.x, ty = threadIdx.y;
    for (int i = ty; i < 32; i += 8)
        t[i][tx] = W[(size_t)(k0 + i) * N + n0 + tx];
    __syncthreads();
    for (int r = ty; r < 32; r += 8) {
        float v = t[tx][r];   // = W[k0+tx][n0+r]
        __nv_bfloat16 h = __float2bfloat16(v);
        size_t o = (size_t)(n0 + r) * K + k0 + tx;
        Th[o] = h;
        Tl[o] = __float2bfloat16(v - __bfloat162float(h));
    }
}

// ---------------- attention kernels (fp32) -----------------------------------
__global__ void attn_cls_kernel(const float* __restrict__ qkv,
                                float* __restrict__ att)
{
    int bh = blockIdx.x;
    int b = bh / H, hh = bh % H;
    int tid = threadIdx.x;

    __shared__ float qs[HD];
    __shared__ float sim[NT];
    __shared__ float red[256];
    __shared__ float red2[4][HD];

    if (tid < HD)
        qs[tid] = qkv[(size_t)(b*NT) * D3 + hh*HD + tid] * QSCALE;
    __syncthreads();

    float lmx = -1e30f;
    for (int j = tid; j < NT; j += 256) {
        const float* kp = qkv + (size_t)(b*NT + j) * D3 + D + hh*HD;
        float s = 0.f;
        #pragma unroll
        for (int d = 0; d < HD; d++) s += qs[d] * kp[d];
        sim[j] = s;
        lmx = fmaxf(lmx, s);
    }
    red[tid] = lmx; __syncthreads();
    for (int st = 128; st > 0; st >>= 1) {
        if (tid < st) red[tid] = fmaxf(red[tid], red[tid+st]);
        __syncthreads();
    }
    float mx = red[0];
    __syncthreads();

    float ls = 0.f;
    for (int j = tid; j < NT; j += 256) {
        float e = __expf(sim[j] - mx);
        sim[j] = e;
        ls += e;
    }
    red[tid] = ls; __syncthreads();
    for (int st = 128; st > 0; st >>= 1) {
        if (tid < st) red[tid] += red[tid+st];
        __syncthreads();
    }
    float linv = 1.f / red[0];
    __syncthreads();

    int d = tid & 63, p = tid >> 6;
    float acc = 0.f;
    for (int j = p; j < NT; j += 4)
        acc += sim[j] * qkv[(size_t)(b*NT + j) * D3 + 2*D + hh*HD + d];
    red2[p][d] = acc;
    __syncthreads();
    if (p == 0) {
        float o = (red2[0][d] + red2[1][d] + red2[2][d] + red2[3][d]) * linv;
        att[(size_t)(b*NT) * D + hh*HD + d] = o;
    }
}

__global__ void attn_time_kernel(const float* __restrict__ qkv,
                                 float* __restrict__ att)
{
    int qid = blockIdx.x * blockDim.x + threadIdx.x;
    int fr = qid % F;
    int sp = (qid / F) % NS;
    int bh = qid / (F * NS);
    int b = bh / H, hh = bh % H;
    int t = 1 + fr*NS + sp;

    const float4* qp = (const float4*)(qkv + (size_t)(b*NT + t) * D3 + hh*HD);
    float4 q4[16];
    #pragma unroll
    for (int i = 0; i < 16; i++) {
        float4 v = qp[i];
        v.x *= QSCALE; v.y *= QSCALE; v.z *= QSCALE; v.w *= QSCALE;
        q4[i] = v;
    }

    float sim[F+1];
    #pragma unroll
    for (int j = 0; j < F+1; j++) {
        int tk = (j == 0) ? 0 : (1 + (j-1)*NS + sp);
        const float4* kp = (const float4*)(qkv + (size_t)(b*NT + tk) * D3 + D + hh*HD);
        float s = 0.f;
        #pragma unroll
        for (int i = 0; i < 16; i++) {
            float4 kk = kp[i];
            s += q4[i].x*kk.x + q4[i].y*kk.y + q4[i].z*kk.z + q4[i].w*kk.w;
        }
        sim[j] = s;
    }
    float mx = sim[0];
    #pragma unroll
    for (int j = 1; j < F+1; j++) mx = fmaxf(mx, sim[j]);
    float l = 0.f;
    #pragma unroll
    for (int j = 0; j < F+1; j++) { sim[j] = __expf(sim[j] - mx); l += sim[j]; }
    float inv = 1.f / l;

    float4 o4[16];
    #pragma unroll
    for (int i = 0; i < 16; i++) o4[i] = make_float4(0.f,0.f,0.f,0.f);
    #pragma unroll
    for (int j = 0; j < F+1; j++) {
        int tk = (j == 0) ? 0 : (1 + (j-1)*NS + sp);
        const float4* vp = (const float4*)(qkv + (size_t)(b*NT + tk) * D3 + 2*D + hh*HD);
        float p = sim[j] * inv;
        #pragma unroll
        for (int i = 0; i < 16; i++) {
            float4 vv = vp[i];
            o4[i].x += p*vv.x; o4[i].y += p*vv.y; o4[i].z += p*vv.z; o4[i].w += p*vv.w;
        }
    }
    float4* op = (float4*)(att + (size_t)(b*NT + t) * D + hh*HD);
    #pragma unroll
    for (int i = 0; i < 16; i++) op[i] = o4[i];
}

__global__ void attn_space_kernel(const float* __restrict__ qkv,
                                  float* __restrict__ att)
{
    int bx = blockIdx.x;
    int bh = bx / F, fr = bx % F;
    int b = bh / H, hh = bh % H;
    int tid = threadIdx.x;
    int sp = tid;
    const int NK = NS + 1;

    __shared__ float Ks[64 * HD];
    __shared__ float Vs[64 * HD];

    float4 q4[16], o4[16];
    float m = -1e30f, l = 0.f;
    if (sp < NS) {
        const float4* qp = (const float4*)(qkv + (size_t)(b*NT + 1 + fr*NS + sp) * D3 + hh*HD);
        #pragma unroll
        for (int i = 0; i < 16; i++) {
            float4 v = qp[i];
            v.x *= QSCALE; v.y *= QSCALE; v.z *= QSCALE; v.w *= QSCALE;
            q4[i] = v;
            o4[i] = make_float4(0.f,0.f,0.f,0.f);
        }
    }

    for (int t0 = 0; t0 < NK; t0 += 64) {
        __syncthreads();
        for (int e = tid; e < 64*HD; e += 256) {
            int jj = e >> 6, d = e & 63;
            int j = t0 + jj;
            float kv = 0.f, vv = 0.f;
            if (j < NK) {
                int tk = (j == 0) ? 0 : (1 + fr*NS + (j-1));
                size_t base = (size_t)(b*NT + tk) * D3 + hh*HD + d;
                kv = qkv[base + D];
                vv = qkv[base + 2*D];
            }
            Ks[e] = kv; Vs[e] = vv;
        }
        __syncthreads();

        if (sp < NS) {
            int lim = min(64, NK - t0);
            for (int jj = 0; jj < lim; jj++) {
                const float4* kr = (const float4*)&Ks[jj * HD];
                float s = 0.f;
                #pragma unroll
                for (int i = 0; i < 16; i++) {
                    float4 kk = kr[i];
                    s += q4[i].x*kk.x + q4[i].y*kk.y + q4[i].z*kk.z + q4[i].w*kk.w;
                }
                float mn  = fmaxf(m, s);
                float fac = __expf(m - mn);
                float p   = __expf(s - mn);
                l = l * fac + p;
                const float4* vr = (const float4*)&Vs[jj * HD];
                #pragma unroll
                for (int i = 0; i < 16; i++) {
                    float4 vv = vr[i];
                    o4[i].x = o4[i].x*fac + p*vv.x;
                    o4[i].y = o4[i].y*fac + p*vv.y;
                    o4[i].z = o4[i].z*fac + p*vv.z;
                    o4[i].w = o4[i].w*fac + p*vv.w;
                }
                m = mn;
            }
        }
    }

    if (sp < NS) {
        float inv = 1.f / l;
        float4* op = (float4*)(att + (size_t)(b*NT + 1 + fr*NS + sp) * D + hh*HD);
        #pragma unroll
        for (int i = 0; i < 16; i++)
            op[i] = make_float4(o4[i].x*inv, o4[i].y*inv, o4[i].z*inv, o4[i].w*inv);
    }
}

// ---------------- host launch ------------------------------------------------
extern "C" void kernel_launch(void* const* d_in, const int* in_sizes, int n_in,
                              void* d_out, int out_size)
{
    const float* x      = (const float*)d_in[0];
    const float* n1g    = (const float*)d_in[1];
    const float* n1b    = (const float*)d_in[2];
    const float* n2g    = (const float*)d_in[3];
    const float* n2b    = (const float*)d_in[4];
    const float* n3g    = (const float*)d_in[5];
    const float* n3b    = (const float*)d_in[6];
    const float* aqkvw  = (const float*)d_in[7];
    const float* aqkvb  = (const float*)d_in[8];
    const float* aprojw = (const float*)d_in[9];
    const float* aprojb = (const float*)d_in[10];
    const float* tqkvw  = (const float*)d_in[11];
    const float* tqkvb  = (const float*)d_in[12];
    const float* tprojw = (const float*)d_in[13];
    const float* tprojb = (const float*)d_in[14];
    const float* fc1w   = (const float*)d_in[15];
    const float* fc1b   = (const float*)d_in[16];
    const float* fc2w   = (const float*)d_in[17];
    const float* fc2b   = (const float*)d_in[18];
    float* out = (float*)d_out;

    __nv_bfloat16 *lnh, *lnl, *atth, *attl, *hidh, *hidl;
    __nv_bfloat16 *wth_tqkv, *wtl_tqkv, *wth_aqkv, *wtl_aqkv;
    __nv_bfloat16 *wth_tproj, *wtl_tproj, *wth_aproj, *wtl_aproj;
    __nv_bfloat16 *wth_fc1, *wtl_fc1, *wth_fc2, *wtl_fc2;
    float *bqkv, *batt, *btres, *bsres, *bhid;
    cudaGetSymbolAddress((void**)&lnh,  g_lnh);  cudaGetSymbolAddress((void**)&lnl,  g_lnl);
    cudaGetSymbolAddress((void**)&atth, g_atth); cudaGetSymbolAddress((void**)&attl, g_attl);
    cudaGetSymbolAddress((void**)&hidh, g_hidh); cudaGetSymbolAddress((void**)&hidl, g_hidl);
    cudaGetSymbolAddress((void**)&bqkv, g_qkv);  cudaGetSymbolAddress((void**)&batt, g_att);
    cudaGetSymbolAddress((void**)&btres,g_tres); cudaGetSymbolAddress((void**)&bsres,g_sres);
    cudaGetSymbolAddress((void**)&bhid, g_hid);
    cudaGetSymbolAddress((void**)&wth_tqkv, g_wth_tqkv); cudaGetSymbolAddress((void**)&wtl_tqkv, g_wtl_tqkv);
    cudaGetSymbolAddress((void**)&wth_aqkv, g_wth_aqkv); cudaGetSymbolAddress((void**)&wtl_aqkv, g_wtl_aqkv);
    cudaGetSymbolAddress((void**)&wth_tproj,g_wth_tproj);cudaGetSymbolAddress((void**)&wtl_tproj,g_wtl_tproj);
    cudaGetSymbolAddress((void**)&wth_aproj,g_wth_aproj);cudaGetSymbolAddress((void**)&wtl_aproj,g_wtl_aproj);
    cudaGetSymbolAddress((void**)&wth_fc1,  g_wth_fc1);  cudaGetSymbolAddress((void**)&wtl_fc1,  g_wtl_fc1);
    cudaGetSymbolAddress((void**)&wth_fc2,  g_wth_fc2);  cudaGetSymbolAddress((void**)&wtl_fc2,  g_wtl_fc2);

    cudaFuncSetAttribute(gemm_bf16x3<0>, cudaFuncAttributeMaxDynamicSharedMemorySize, SMEM_GEMM);
    cudaFuncSetAttribute(gemm_bf16x3<1>, cudaFuncAttributeMaxDynamicSharedMemorySize, SMEM_GEMM);
    cudaFuncSetAttribute(gemm_bf16x3<2>, cudaFuncAttributeMaxDynamicSharedMemorySize, SMEM_GEMM);

    const int MT = (M + BM - 1) / BM;    // 99
    dim3 tb(32, 8);

    // ---- weight transpose + split ----
    tsplit_kernel<<<dim3(D3/32, D/32), tb>>>(tqkvw, wth_tqkv, wtl_tqkv, D, D3);
    tsplit_kernel<<<dim3(D3/32, D/32), tb>>>(aqkvw, wth_aqkv, wtl_aqkv, D, D3);
    tsplit_kernel<<<dim3(D/32,  D/32), tb>>>(tprojw, wth_tproj, wtl_tproj, D, D);
    tsplit_kernel<<<dim3(D/32,  D/32), tb>>>(aprojw, wth_aproj, wtl_aproj, D, D);
    tsplit_kernel<<<dim3(D4/32, D/32), tb>>>(fc1w, wth_fc1, wtl_fc1, D, D4);
    tsplit_kernel<<<dim3(D/32, D4/32), tb>>>(fc2w, wth_fc2, wtl_fc2, D4, D);

    const int nTimeBlocks = (B*H*NS*F) / 256;       // 588
    const int nSplitD  = ((M*D/4)  + 255) / 256;
    const int nSplitD4 = ((M*D4/4) + 255) / 256;

    // ---- time attention branch ----
    ln_split_kernel<<<M, 256>>>(x, n3g, n3b, lnh, lnl);
    gemm_bf16x3<0><<<dim3(D3/BN, MT), 256, SMEM_GEMM>>>(lnh, lnl, wth_tqkv, wtl_tqkv, tqkvb, nullptr, bqkv, M, D, D3);
    attn_cls_kernel <<<B*H, 256>>>(bqkv, batt);
    attn_time_kernel<<<nTimeBlocks, 256>>>(bqkv, batt);
    split_kernel<<<nSplitD, 256>>>((const float4*)batt, (__nv_bfloat162*)atth, (__nv_bfloat162*)attl, M*D/4);
    gemm_bf16x3<1><<<dim3(D/BN, MT), 256, SMEM_GEMM>>>(atth, attl, wth_tproj, wtl_tproj, tprojb, x, btres, M, D, D);

    // ---- space attention branch ----
    ln_split_kernel<<<M, 256>>>(btres, n1g, n1b, lnh, lnl);
    gemm_bf16x3<0><<<dim3(D3/BN, MT), 256, SMEM_GEMM>>>(lnh, lnl, wth_aqkv, wtl_aqkv, aqkvb, nullptr, bqkv, M, D, D3);
    attn_cls_kernel  <<<B*H, 256>>>(bqkv, batt);
    attn_space_kernel<<<B*H*F, 256>>>(bqkv, batt);
    split_kernel<<<nSplitD, 256>>>((const float4*)batt, (__nv_bfloat162*)atth, (__nv_bfloat162*)attl, M*D/4);
    gemm_bf16x3<1><<<dim3(D/BN, MT), 256, SMEM_GEMM>>>(atth, attl, wth_aproj, wtl_aproj, aprojb, x, bsres, M, D, D);

    // ---- MLP ----
    ln_split_kernel<<<M, 256>>>(bsres, n2g, n2b, lnh, lnl);
    gemm_bf16x3<2><<<dim3(D4/BN, MT), 256, SMEM_GEMM>>>(lnh, lnl, wth_fc1, wtl_fc1, fc1b, nullptr, bhid, M, D, D4);
    split_kernel<<<nSplitD4, 256>>>((const float4*)bhid, (__nv_bfloat162*)hidh, (__nv_bfloat162*)hidl, M*D4/4);
    gemm_bf16x3<1><<<dim3(D/BN, MT), 256, SMEM_GEMM>>>(hidh, hidl, wth_fc2, wtl_fc2, fc2b, bsres, out, M, D4, D);
}

// round 4
// speedup vs baseline: 2.2543x; 1.0015x over previous
#include <cuda_runtime.h>
#include <cuda_bf16.h>
#include <math.h>
#include <cstdint>

// ---------------- problem constants ----------------------------------------
constexpr int B   = 8;
constexpr int F   = 8;
constexpr int NS  = 196;
constexpr int NT  = 1 + F*NS;   // 1569
constexpr int D   = 768;
constexpr int H   = 12;
constexpr int HD  = 64;
constexpr int D3  = 3*D;        // 2304
constexpr int D4  = 4*D;        // 3072
constexpr int M   = B*NT;       // 12552
constexpr float LN_EPS = 1e-5f;
constexpr float QSCALE = 0.125f;

// ---------------- scratch (device globals; no allocation) ------------------
__device__ __nv_bfloat16 g_lnh [(size_t)M * D];
__device__ __nv_bfloat16 g_lnl [(size_t)M * D];
__device__ float         g_qkv [(size_t)M * D3];
__device__ __nv_bfloat16 g_atth[(size_t)M * D];
__device__ __nv_bfloat16 g_attl[(size_t)M * D];
__device__ float         g_tres[(size_t)M * D];
__device__ float         g_sres[(size_t)M * D];
__device__ __nv_bfloat16 g_hidh[(size_t)M * D4];
__device__ __nv_bfloat16 g_hidl[(size_t)M * D4];
// transposed+split weights: Wt[n][k] = W[k][n]
__device__ __nv_bfloat16 g_wth_tqkv [(size_t)D3*D], g_wtl_tqkv [(size_t)D3*D];
__device__ __nv_bfloat16 g_wth_aqkv [(size_t)D3*D], g_wtl_aqkv [(size_t)D3*D];
__device__ __nv_bfloat16 g_wth_tproj[(size_t)D*D],  g_wtl_tproj[(size_t)D*D];
__device__ __nv_bfloat16 g_wth_aproj[(size_t)D*D],  g_wtl_aproj[(size_t)D*D];
__device__ __nv_bfloat16 g_wth_fc1  [(size_t)D4*D], g_wtl_fc1  [(size_t)D4*D];
__device__ __nv_bfloat16 g_wth_fc2  [(size_t)D*D4], g_wtl_fc2  [(size_t)D*D4];

// ---------------- helpers ----------------------------------------------------
__device__ __forceinline__ uint32_t smem_to_u32(const void* p) {
    uint32_t a;
    asm("{ .reg .u64 t; cvta.to.shared.u64 t, %1; cvt.u32.u64 %0, t; }"
        : "=r"(a) : "l"(p));
    return a;
}
__device__ __forceinline__ void cp_async16(uint32_t dst, const void* src, bool valid) {
    int sz = valid ? 16 : 0;
    asm volatile("cp.async.cg.shared.global [%0], [%1], 16, %2;"
                 :: "r"(dst), "l"(src), "r"(sz) : "memory");
}
#define CP_COMMIT()  asm volatile("cp.async.commit_group;" ::: "memory")
#define CP_WAIT(n)   asm volatile("cp.async.wait_group %0;" :: "n"(n) : "memory")

__device__ __forceinline__ void ldsm_x4(uint32_t& r0, uint32_t& r1, uint32_t& r2, uint32_t& r3, uint32_t addr) {
    asm volatile("ldmatrix.sync.aligned.m8n8.x4.shared.b16 {%0,%1,%2,%3}, [%4];"
                 : "=r"(r0), "=r"(r1), "=r"(r2), "=r"(r3) : "r"(addr));
}
__device__ __forceinline__ void ldsm_x2(uint32_t& r0, uint32_t& r1, uint32_t addr) {
    asm volatile("ldmatrix.sync.aligned.m8n8.x2.shared.b16 {%0,%1}, [%2];"
                 : "=r"(r0), "=r"(r1) : "r"(addr));
}
__device__ __forceinline__ void mma16816(float* c, const uint32_t* a, const uint32_t* b) {
    asm volatile(
        "mma.sync.aligned.m16n8k16.row.col.f32.bf16.bf16.f32 "
        "{%0,%1,%2,%3}, {%4,%5,%6,%7}, {%8,%9}, {%0,%1,%2,%3};"
        : "+f"(c[0]), "+f"(c[1]), "+f"(c[2]), "+f"(c[3])
        : "r"(a[0]), "r"(a[1]), "r"(a[2]), "r"(a[3]), "r"(b[0]), "r"(b[1]));
}
__device__ __forceinline__ float gelu_exact(float v) {
    return 0.5f * v * (1.f + erff(v * 0.70710678118654752f));
}
__device__ __forceinline__ __nv_bfloat162 split2(float v0, float v1, __nv_bfloat162& lo) {
    __nv_bfloat16 h0 = __float2bfloat16(v0), h1 = __float2bfloat16(v1);
    lo = __halves2bfloat162(__float2bfloat16(v0 - __bfloat162float(h0)),
                            __float2bfloat16(v1 - __bfloat162float(h1)));
    return __halves2bfloat162(h0, h1);
}

// ---------------- GEMM (mma.sync bf16x3 split, 4-stage pipeline) -------------
constexpr int BM = 128, BN = 128, BK = 32;
constexpr int RSB = 80;                // padded row stride in bytes (40 bf16)
constexpr int MAT_B = 128 * RSB;       // 10240 B per matrix tile
constexpr int STAGE_B = 4 * MAT_B;     // Ah, Al, Bh, Bl = 40960
constexpr int NSTAGE = 4;
constexpr int SMEM_GEMM = NSTAGE * STAGE_B; // 163840 B

// EPI: 0 = bias (fp32 out), 1 = bias+residual (fp32 out), 3 = bias+GELU -> bf16 hi/lo out
template<int EPI>
__global__ void __launch_bounds__(256, 1)
gemm_bf16x3(const __nv_bfloat16* __restrict__ Ah, const __nv_bfloat16* __restrict__ Al,
            const __nv_bfloat16* __restrict__ Bh, const __nv_bfloat16* __restrict__ Bl,
            const float* __restrict__ bias, const float* __restrict__ R,
            float* __restrict__ C,
            __nv_bfloat16* __restrict__ Ch, __nv_bfloat16* __restrict__ Cl,
            int Mr, int K, int Nc)
{
    extern __shared__ char smem[];
    const uint32_t sb = smem_to_u32(smem);
    const int tid = threadIdx.x;
    const int wid = tid >> 5, lane = tid & 31;
    const int wm = wid & 1, wn = wid >> 1;          // warp tile: (wm*64, wn*32)
    const int bm = blockIdx.y * BM, bn = blockIdx.x * BN;

    float acc[4][4][4];
    #pragma unroll
    for (int i = 0; i < 4; i++)
        #pragma unroll
        for (int j = 0; j < 4; j++)
            #pragma unroll
            for (int q = 0; q < 4; q++) acc[i][j][q] = 0.f;

    auto load_stage = [&](int stage, int k0) {
        uint32_t base = sb + stage * STAGE_B;
        #pragma unroll
        for (int i = 0; i < 2; i++) {
            int idx = tid + i*256;
            int r = idx >> 2, cb = (idx & 3) << 4;
            int gr = bm + r;
            bool v = gr < Mr;
            const char* srcH = (const char*)(Ah + (size_t)(v ? gr : 0) * K + k0) + cb;
            const char* srcL = (const char*)(Al + (size_t)(v ? gr : 0) * K + k0) + cb;
            cp_async16(base + 0*MAT_B + r*RSB + cb, srcH, v);
            cp_async16(base + 1*MAT_B + r*RSB + cb, srcL, v);
        }
        #pragma unroll
        for (int i = 0; i < 2; i++) {
            int idx = tid + i*256;
            int r = idx >> 2, cb = (idx & 3) << 4;
            const char* srcH = (const char*)(Bh + (size_t)(bn + r) * K + k0) + cb;
            const char* srcL = (const char*)(Bl + (size_t)(bn + r) * K + k0) + cb;
            cp_async16(base + 2*MAT_B + r*RSB + cb, srcH, true);
            cp_async16(base + 3*MAT_B + r*RSB + cb, srcL, true);
        }
        CP_COMMIT();
    };

    const int NC = K / BK;   // >= 24 always
    load_stage(0, 0);
    load_stage(1, BK);
    load_stage(2, 2*BK);

    const int aRow = (lane & 15);
    const int aColB = (lane >> 4) * 16;
    const int bRow = (lane & 7);
    const int bColB = ((lane >> 3) & 1) * 16;

    for (int c = 0; c < NC; c++) {
        CP_WAIT(2);
        __syncthreads();
        if (c + 3 < NC) load_stage((c + 3) & 3, (c + 3) * BK);

        uint32_t st = sb + (c & 3) * STAGE_B;
        uint32_t aHb = st + 0*MAT_B, aLb = st + 1*MAT_B;
        uint32_t bHb = st + 2*MAT_B, bLb = st + 3*MAT_B;

        #pragma unroll
        for (int kk = 0; kk < 2; kk++) {
            uint32_t ah[4][4], al[4][4], bh[4][2], bl[4][2];
            #pragma unroll
            for (int mt = 0; mt < 4; mt++) {
                uint32_t off = (uint32_t)((wm*64 + mt*16 + aRow) * RSB + kk*32 + aColB);
                ldsm_x4(ah[mt][0], ah[mt][1], ah[mt][2], ah[mt][3], aHb + off);
                ldsm_x4(al[mt][0], al[mt][1], al[mt][2], al[mt][3], aLb + off);
            }
            #pragma unroll
            for (int nt = 0; nt < 4; nt++) {
                uint32_t off = (uint32_t)((wn*32 + nt*8 + bRow) * RSB + kk*32 + bColB);
                ldsm_x2(bh[nt][0], bh[nt][1], bHb + off);
                ldsm_x2(bl[nt][0], bl[nt][1], bLb + off);
            }
            #pragma unroll
            for (int mt = 0; mt < 4; mt++) {
                #pragma unroll
                for (int nt = 0; nt < 4; nt++) {
                    mma16816(acc[mt][nt], ah[mt], bh[nt]);
                    mma16816(acc[mt][nt], ah[mt], bl[nt]);
                    mma16816(acc[mt][nt], al[mt], bh[nt]);
                }
            }
        }
    }

    const int er = lane >> 2, ec = (lane & 3) * 2;
    #pragma unroll
    for (int mt = 0; mt < 4; mt++) {
        int r0 = bm + wm*64 + mt*16 + er;
        int r1 = r0 + 8;
        #pragma unroll
        for (int nt = 0; nt < 4; nt++) {
            int cc = bn + wn*32 + nt*8 + ec;
            float b0 = bias[cc], b1 = bias[cc + 1];
            if (r0 < Mr) {
                float v0 = acc[mt][nt][0] + b0;
                float v1 = acc[mt][nt][1] + b1;
                size_t off = (size_t)r0 * Nc + cc;
                if (EPI == 1) { v0 += R[off]; v1 += R[off + 1]; }
                if (EPI == 3) {
                    v0 = gelu_exact(v0); v1 = gelu_exact(v1);
                    __nv_bfloat162 lo, hi = split2(v0, v1, lo);
                    *(__nv_bfloat162*)&Ch[off] = hi;
                    *(__nv_bfloat162*)&Cl[off] = lo;
                } else {
                    C[off] = v0; C[off + 1] = v1;
                }
            }
            if (r1 < Mr) {
                float v2 = acc[mt][nt][2] + b0;
                float v3 = acc[mt][nt][3] + b1;
                size_t off = (size_t)r1 * Nc + cc;
                if (EPI == 1) { v2 += R[off]; v3 += R[off + 1]; }
                if (EPI == 3) {
                    v2 = gelu_exact(v2); v3 = gelu_exact(v3);
                    __nv_bfloat162 lo, hi = split2(v2, v3, lo);
                    *(__nv_bfloat162*)&Ch[off] = hi;
                    *(__nv_bfloat162*)&Cl[off] = lo;
                } else {
                    C[off] = v2; C[off + 1] = v3;
                }
            }
        }
    }
}

// ---------------- LayerNorm with bf16 hi/lo split output --------------------
__global__ void ln_split_kernel(const float* __restrict__ X,
                                const float* __restrict__ gam,
                                const float* __restrict__ bet,
                                __nv_bfloat16* __restrict__ Hi,
                                __nv_bfloat16* __restrict__ Lo)
{
    int row = blockIdx.x;
    const float* x = X + (size_t)row * D;
    int tid = threadIdx.x;

    float s = 0.f, ss = 0.f;
    for (int i = tid; i < D; i += 256) { float v = x[i]; s += v; ss += v*v; }
    __shared__ float rs[32], rss[32];
    for (int o = 16; o > 0; o >>= 1) {
        s  += __shfl_xor_sync(0xffffffffu, s,  o);
        ss += __shfl_xor_sync(0xffffffffu, ss, o);
    }
    int wid = tid >> 5, lid = tid & 31;
    if (lid == 0) { rs[wid] = s; rss[wid] = ss; }
    __syncthreads();
    __shared__ float s_mean, s_inv;
    if (tid == 0) {
        float ts = 0.f, tss = 0.f;
        for (int w = 0; w < 8; w++) { ts += rs[w]; tss += rss[w]; }
        float mean = ts * (1.f/D);
        float var  = tss * (1.f/D) - mean*mean;
        s_mean = mean; s_inv = rsqrtf(var + LN_EPS);
    }
    __syncthreads();
    float mean = s_mean, inv = s_inv;
    for (int i = tid; i < D; i += 256) {
        float v = (x[i] - mean) * inv * gam[i] + bet[i];
        __nv_bfloat16 h = __float2bfloat16(v);
        Hi[(size_t)row*D + i] = h;
        Lo[(size_t)row*D + i] = __float2bfloat16(v - __bfloat162float(h));
    }
}

// ---------------- transpose + split: W[K][N] -> Th/Tl[N][K] ------------------
__global__ void tsplit_kernel(const float* __restrict__ W,
                              __nv_bfloat16* __restrict__ Th,
                              __nv_bfloat16* __restrict__ Tl, int K, int N)
{
    __shared__ float t[32][33];
    int n0 = blockIdx.x * 32, k0 = blockIdx.y * 32;
    int tx = threadIdx.x, ty = threadIdx.y;
    for (int i = ty; i < 32; i += 8)
        t[i][tx] = W[(size_t)(k0 + i) * N + n0 + tx];
    __syncthreads();
    for (int r = ty; r < 32; r += 8) {
        float v = t[tx][r];
        __nv_bfloat16 h = __float2bfloat16(v);
        size_t o = (size_t)(n0 + r) * K + k0 + tx;
        Th[o] = h;
        Tl[o] = __float2bfloat16(v - __bfloat162float(h));
    }
}

// ---------------- attention kernels (fp32 math, bf16 hi/lo output) ----------
__global__ void attn_cls_kernel(const float* __restrict__ qkv,
                                __nv_bfloat16* __restrict__ Oh,
                                __nv_bfloat16* __restrict__ Ol)
{
    int bh = blockIdx.x;
    int b = bh / H, hh = bh % H;
    int tid = threadIdx.x;

    __shared__ float qs[HD];
    __shared__ float sim[NT];
    __shared__ float red[256];
    __shared__ float red2[4][HD];

    if (tid < HD)
        qs[tid] = qkv[(size_t)(b*NT) * D3 + hh*HD + tid] * QSCALE;
    __syncthreads();

    float lmx = -1e30f;
    for (int j = tid; j < NT; j += 256) {
        const float* kp = qkv + (size_t)(b*NT + j) * D3 + D + hh*HD;
        float s = 0.f;
        #pragma unroll
        for (int d = 0; d < HD; d++) s += qs[d] * kp[d];
        sim[j] = s;
        lmx = fmaxf(lmx, s);
    }
    red[tid] = lmx; __syncthreads();
    for (int st = 128; st > 0; st >>= 1) {
        if (tid < st) red[tid] = fmaxf(red[tid], red[tid+st]);
        __syncthreads();
    }
    float mx = red[0];
    __syncthreads();

    float ls = 0.f;
    for (int j = tid; j < NT; j += 256) {
        float e = __expf(sim[j] - mx);
        sim[j] = e;
        ls += e;
    }
    red[tid] = ls; __syncthreads();
    for (int st = 128; st > 0; st >>= 1) {
        if (tid < st) red[tid] += red[tid+st];
        __syncthreads();
    }
    float linv = 1.f / red[0];
    __syncthreads();

    int d = tid & 63, p = tid >> 6;
    float acc = 0.f;
    for (int j = p; j < NT; j += 4)
        acc += sim[j] * qkv[(size_t)(b*NT + j) * D3 + 2*D + hh*HD + d];
    red2[p][d] = acc;
    __syncthreads();
    if (p == 0) {
        float o = (red2[0][d] + red2[1][d] + red2[2][d] + red2[3][d]) * linv;
        size_t idx = (size_t)(b*NT) * D + hh*HD + d;
        __nv_bfloat16 h = __float2bfloat16(o);
        Oh[idx] = h;
        Ol[idx] = __float2bfloat16(o - __bfloat162float(h));
    }
}

__global__ void attn_time_kernel(const float* __restrict__ qkv,
                                 __nv_bfloat16* __restrict__ Oh,
                                 __nv_bfloat16* __restrict__ Ol)
{
    int qid = blockIdx.x * blockDim.x + threadIdx.x;
    int fr = qid % F;
    int sp = (qid / F) % NS;
    int bh = qid / (F * NS);
    int b = bh / H, hh = bh % H;
    int t = 1 + fr*NS + sp;

    const float4* qp = (const float4*)(qkv + (size_t)(b*NT + t) * D3 + hh*HD);
    float4 q4[16];
    #pragma unroll
    for (int i = 0; i < 16; i++) {
        float4 v = qp[i];
        v.x *= QSCALE; v.y *= QSCALE; v.z *= QSCALE; v.w *= QSCALE;
        q4[i] = v;
    }

    float sim[F+1];
    #pragma unroll
    for (int j = 0; j < F+1; j++) {
        int tk = (j == 0) ? 0 : (1 + (j-1)*NS + sp);
        const float4* kp = (const float4*)(qkv + (size_t)(b*NT + tk) * D3 + D + hh*HD);
        float s = 0.f;
        #pragma unroll
        for (int i = 0; i < 16; i++) {
            float4 kk = kp[i];
            s += q4[i].x*kk.x + q4[i].y*kk.y + q4[i].z*kk.z + q4[i].w*kk.w;
        }
        sim[j] = s;
    }
    float mx = sim[0];
    #pragma unroll
    for (int j = 1; j < F+1; j++) mx = fmaxf(mx, sim[j]);
    float l = 0.f;
    #pragma unroll
    for (int j = 0; j < F+1; j++) { sim[j] = __expf(sim[j] - mx); l += sim[j]; }
    float inv = 1.f / l;

    float4 o4[16];
    #pragma unroll
    for (int i = 0; i < 16; i++) o4[i] = make_float4(0.f,0.f,0.f,0.f);
    #pragma unroll
    for (int j = 0; j < F+1; j++) {
        int tk = (j == 0) ? 0 : (1 + (j-1)*NS + sp);
        const float4* vp = (const float4*)(qkv + (size_t)(b*NT + tk) * D3 + 2*D + hh*HD);
        float p = sim[j] * inv;
        #pragma unroll
        for (int i = 0; i < 16; i++) {
            float4 vv = vp[i];
            o4[i].x += p*vv.x; o4[i].y += p*vv.y; o4[i].z += p*vv.z; o4[i].w += p*vv.w;
        }
    }
    size_t base = (size_t)(b*NT + t) * D + hh*HD;
    __nv_bfloat162* oh = (__nv_bfloat162*)&Oh[base];
    __nv_bfloat162* ol = (__nv_bfloat162*)&Ol[base];
    #pragma unroll
    for (int i = 0; i < 16; i++) {
        __nv_bfloat162 lo0, hi0 = split2(o4[i].x, o4[i].y, lo0);
        __nv_bfloat162 lo1, hi1 = split2(o4[i].z, o4[i].w, lo1);
        oh[2*i] = hi0; oh[2*i+1] = hi1;
        ol[2*i] = lo0; ol[2*i+1] = lo1;
    }
}

__global__ void attn_space_kernel(const float* __restrict__ qkv,
                                  __nv_bfloat16* __restrict__ Oh,
                                  __nv_bfloat16* __restrict__ Ol)
{
    int bx = blockIdx.x;
    int bh = bx / F, fr = bx % F;
    int b = bh / H, hh = bh % H;
    int tid = threadIdx.x;
    int sp = tid;
    const int NK = NS + 1;

    __shared__ float Ks[64 * HD];
    __shared__ float Vs[64 * HD];

    float4 q4[16], o4[16];
    float m = -1e30f, l = 0.f;
    if (sp < NS) {
        const float4* qp = (const float4*)(qkv + (size_t)(b*NT + 1 + fr*NS + sp) * D3 + hh*HD);
        #pragma unroll
        for (int i = 0; i < 16; i++) {
            float4 v = qp[i];
            v.x *= QSCALE; v.y *= QSCALE; v.z *= QSCALE; v.w *= QSCALE;
            q4[i] = v;
            o4[i] = make_float4(0.f,0.f,0.f,0.f);
        }
    }

    for (int t0 = 0; t0 < NK; t0 += 64) {
        __syncthreads();
        for (int e = tid; e < 64*HD; e += 256) {
            int jj = e >> 6, d = e & 63;
            int j = t0 + jj;
            float kv = 0.f, vv = 0.f;
            if (j < NK) {
                int tk = (j == 0) ? 0 : (1 + fr*NS + (j-1));
                size_t base = (size_t)(b*NT + tk) * D3 + hh*HD + d;
                kv = qkv[base + D];
                vv = qkv[base + 2*D];
            }
            Ks[e] = kv; Vs[e] = vv;
        }
        __syncthreads();

        if (sp < NS) {
            int lim = min(64, NK - t0);
            for (int jj = 0; jj < lim; jj++) {
                const float4* kr = (const float4*)&Ks[jj * HD];
                float s = 0.f;
                #pragma unroll
                for (int i = 0; i < 16; i++) {
                    float4 kk = kr[i];
                    s += q4[i].x*kk.x + q4[i].y*kk.y + q4[i].z*kk.z + q4[i].w*kk.w;
                }
                float mn  = fmaxf(m, s);
                float fac = __expf(m - mn);
                float p   = __expf(s - mn);
                l = l * fac + p;
                const float4* vr = (const float4*)&Vs[jj * HD];
                #pragma unroll
                for (int i = 0; i < 16; i++) {
                    float4 vv = vr[i];
                    o4[i].x = o4[i].x*fac + p*vv.x;
                    o4[i].y = o4[i].y*fac + p*vv.y;
                    o4[i].z = o4[i].z*fac + p*vv.z;
                    o4[i].w = o4[i].w*fac + p*vv.w;
                }
                m = mn;
            }
        }
    }

    if (sp < NS) {
        float inv = 1.f / l;
        size_t base = (size_t)(b*NT + 1 + fr*NS + sp) * D + hh*HD;
        __nv_bfloat162* oh = (__nv_bfloat162*)&Oh[base];
        __nv_bfloat162* ol = (__nv_bfloat162*)&Ol[base];
        #pragma unroll
        for (int i = 0; i < 16; i++) {
            __nv_bfloat162 lo0, hi0 = split2(o4[i].x*inv, o4[i].y*inv, lo0);
            __nv_bfloat162 lo1, hi1 = split2(o4[i].z*inv, o4[i].w*inv, lo1);
            oh[2*i] = hi0; oh[2*i+1] = hi1;
            ol[2*i] = lo0; ol[2*i+1] = lo1;
        }
    }
}

// ---------------- host launch ------------------------------------------------
extern "C" void kernel_launch(void* const* d_in, const int* in_sizes, int n_in,
                              void* d_out, int out_size)
{
    const float* x      = (const float*)d_in[0];
    const float* n1g    = (const float*)d_in[1];
    const float* n1b    = (const float*)d_in[2];
    const float* n2g    = (const float*)d_in[3];
    const float* n2b    = (const float*)d_in[4];
    const float* n3g    = (const float*)d_in[5];
    const float* n3b    = (const float*)d_in[6];
    const float* aqkvw  = (const float*)d_in[7];
    const float* aqkvb  = (const float*)d_in[8];
    const float* aprojw = (const float*)d_in[9];
    const float* aprojb = (const float*)d_in[10];
    const float* tqkvw  = (const float*)d_in[11];
    const float* tqkvb  = (const float*)d_in[12];
    const float* tprojw = (const float*)d_in[13];
    const float* tprojb = (const float*)d_in[14];
    const float* fc1w   = (const float*)d_in[15];
    const float* fc1b   = (const float*)d_in[16];
    const float* fc2w   = (const float*)d_in[17];
    const float* fc2b   = (const float*)d_in[18];
    float* out = (float*)d_out;

    __nv_bfloat16 *lnh, *lnl, *atth, *attl, *hidh, *hidl;
    __nv_bfloat16 *wth_tqkv, *wtl_tqkv, *wth_aqkv, *wtl_aqkv;
    __nv_bfloat16 *wth_tproj, *wtl_tproj, *wth_aproj, *wtl_aproj;
    __nv_bfloat16 *wth_fc1, *wtl_fc1, *wth_fc2, *wtl_fc2;
    float *bqkv, *btres, *bsres;
    cudaGetSymbolAddress((void**)&lnh,  g_lnh);  cudaGetSymbolAddress((void**)&lnl,  g_lnl);
    cudaGetSymbolAddress((void**)&atth, g_atth); cudaGetSymbolAddress((void**)&attl, g_attl);
    cudaGetSymbolAddress((void**)&hidh, g_hidh); cudaGetSymbolAddress((void**)&hidl, g_hidl);
    cudaGetSymbolAddress((void**)&bqkv, g_qkv);
    cudaGetSymbolAddress((void**)&btres,g_tres); cudaGetSymbolAddress((void**)&bsres,g_sres);
    cudaGetSymbolAddress((void**)&wth_tqkv, g_wth_tqkv); cudaGetSymbolAddress((void**)&wtl_tqkv, g_wtl_tqkv);
    cudaGetSymbolAddress((void**)&wth_aqkv, g_wth_aqkv); cudaGetSymbolAddress((void**)&wtl_aqkv, g_wtl_aqkv);
    cudaGetSymbolAddress((void**)&wth_tproj,g_wth_tproj);cudaGetSymbolAddress((void**)&wtl_tproj,g_wtl_tproj);
    cudaGetSymbolAddress((void**)&wth_aproj,g_wth_aproj);cudaGetSymbolAddress((void**)&wtl_aproj,g_wtl_aproj);
    cudaGetSymbolAddress((void**)&wth_fc1,  g_wth_fc1);  cudaGetSymbolAddress((void**)&wtl_fc1,  g_wtl_fc1);
    cudaGetSymbolAddress((void**)&wth_fc2,  g_wth_fc2);  cudaGetSymbolAddress((void**)&wtl_fc2,  g_wtl_fc2);

    cudaFuncSetAttribute(gemm_bf16x3<0>, cudaFuncAttributeMaxDynamicSharedMemorySize, SMEM_GEMM);
    cudaFuncSetAttribute(gemm_bf16x3<1>, cudaFuncAttributeMaxDynamicSharedMemorySize, SMEM_GEMM);
    cudaFuncSetAttribute(gemm_bf16x3<3>, cudaFuncAttributeMaxDynamicSharedMemorySize, SMEM_GEMM);

    const int MT = (M + BM - 1) / BM;    // 99
    dim3 tb(32, 8);

    // ---- weight transpose + split ----
    tsplit_kernel<<<dim3(D3/32, D/32), tb>>>(tqkvw, wth_tqkv, wtl_tqkv, D, D3);
    tsplit_kernel<<<dim3(D3/32, D/32), tb>>>(aqkvw, wth_aqkv, wtl_aqkv, D, D3);
    tsplit_kernel<<<dim3(D/32,  D/32), tb>>>(tprojw, wth_tproj, wtl_tproj, D, D);
    tsplit_kernel<<<dim3(D/32,  D/32), tb>>>(aprojw, wth_aproj, wtl_aproj, D, D);
    tsplit_kernel<<<dim3(D4/32, D/32), tb>>>(fc1w, wth_fc1, wtl_fc1, D, D4);
    tsplit_kernel<<<dim3(D/32, D4/32), tb>>>(fc2w, wth_fc2, wtl_fc2, D4, D);

    const int nTimeBlocks = (B*H*NS*F) / 256;   // 588

    // ---- time attention branch ----
    ln_split_kernel<<<M, 256>>>(x, n3g, n3b, lnh, lnl);
    gemm_bf16x3<0><<<dim3(D3/BN, MT), 256, SMEM_GEMM>>>(lnh, lnl, wth_tqkv, wtl_tqkv, tqkvb, nullptr, bqkv, nullptr, nullptr, M, D, D3);
    attn_cls_kernel <<<B*H, 256>>>(bqkv, atth, attl);
    attn_time_kernel<<<nTimeBlocks, 256>>>(bqkv, atth, attl);
    gemm_bf16x3<1><<<dim3(D/BN, MT), 256, SMEM_GEMM>>>(atth, attl, wth_tproj, wtl_tproj, tprojb, x, btres, nullptr, nullptr, M, D, D);

    // ---- space attention branch ----
    ln_split_kernel<<<M, 256>>>(btres, n1g, n1b, lnh, lnl);
    gemm_bf16x3<0><<<dim3(D3/BN, MT), 256, SMEM_GEMM>>>(lnh, lnl, wth_aqkv, wtl_aqkv, aqkvb, nullptr, bqkv, nullptr, nullptr, M, D, D3);
    attn_cls_kernel  <<<B*H, 256>>>(bqkv, atth, attl);
    attn_space_kernel<<<B*H*F, 256>>>(bqkv, atth, attl);
    gemm_bf16x3<1><<<dim3(D/BN, MT), 256, SMEM_GEMM>>>(atth, attl, wth_aproj, wtl_aproj, aprojb, x, bsres, nullptr, nullptr, M, D, D);

    // ---- MLP ----
    ln_split_kernel<<<M, 256>>>(bsres, n2g, n2b, lnh, lnl);
    gemm_bf16x3<3><<<dim3(D4/BN, MT), 256, SMEM_GEMM>>>(lnh, lnl, wth_fc1, wtl_fc1, fc1b, nullptr, nullptr, hidh, hidl, M, D, D4);
    gemm_bf16x3<1><<<dim3(D/BN, MT), 256, SMEM_GEMM>>>(hidh, hidl, wth_fc2, wtl_fc2, fc2b, bsres, out, nullptr, nullptr, M, D4, D);
}

// round 5
// speedup vs baseline: 2.2923x; 1.0169x over previous
#include <cuda_runtime.h>
#include <cuda_bf16.h>
#include <math.h>
#include <cstdint>

// ---------------- problem constants ----------------------------------------
constexpr int B   = 8;
constexpr int F   = 8;
constexpr int NS  = 196;
constexpr int NT  = 1 + F*NS;   // 1569
constexpr int D   = 768;
constexpr int H   = 12;
constexpr int HD  = 64;
constexpr int D3  = 3*D;        // 2304
constexpr int D4  = 4*D;        // 3072
constexpr int M   = B*NT;       // 12552
constexpr float LN_EPS = 1e-5f;
constexpr float QSCALE = 0.125f;

// ---------------- scratch (device globals; no allocation) ------------------
__device__ __nv_bfloat16 g_lnh [(size_t)M * D];
__device__ __nv_bfloat16 g_lnl [(size_t)M * D];
__device__ float         g_qkv [(size_t)M * D3];
__device__ __nv_bfloat16 g_atth[(size_t)M * D];
__device__ __nv_bfloat16 g_attl[(size_t)M * D];
__device__ float         g_tres[(size_t)M * D];
__device__ float         g_sres[(size_t)M * D];
__device__ __nv_bfloat16 g_hidh[(size_t)M * D4];
__device__ __nv_bfloat16 g_hidl[(size_t)M * D4];
// transposed+split weights: Wt[n][k] = W[k][n]
__device__ __nv_bfloat16 g_wth_tqkv [(size_t)D3*D], g_wtl_tqkv [(size_t)D3*D];
__device__ __nv_bfloat16 g_wth_aqkv [(size_t)D3*D], g_wtl_aqkv [(size_t)D3*D];
__device__ __nv_bfloat16 g_wth_tproj[(size_t)D*D],  g_wtl_tproj[(size_t)D*D];
__device__ __nv_bfloat16 g_wth_aproj[(size_t)D*D],  g_wtl_aproj[(size_t)D*D];
__device__ __nv_bfloat16 g_wth_fc1  [(size_t)D4*D], g_wtl_fc1  [(size_t)D4*D];
__device__ __nv_bfloat16 g_wth_fc2  [(size_t)D*D4], g_wtl_fc2  [(size_t)D*D4];

// ---------------- helpers ----------------------------------------------------
__device__ __forceinline__ uint32_t smem_to_u32(const void* p) {
    uint32_t a;
    asm("{ .reg .u64 t; cvta.to.shared.u64 t, %1; cvt.u32.u64 %0, t; }"
        : "=r"(a) : "l"(p));
    return a;
}
__device__ __forceinline__ void cp_async16(uint32_t dst, const void* src, bool valid) {
    int sz = valid ? 16 : 0;
    asm volatile("cp.async.cg.shared.global [%0], [%1], 16, %2;"
                 :: "r"(dst), "l"(src), "r"(sz) : "memory");
}
#define CP_COMMIT()  asm volatile("cp.async.commit_group;" ::: "memory")
#define CP_WAIT(n)   asm volatile("cp.async.wait_group %0;" :: "n"(n) : "memory")

__device__ __forceinline__ void ldsm_x4(uint32_t& r0, uint32_t& r1, uint32_t& r2, uint32_t& r3, uint32_t addr) {
    asm volatile("ldmatrix.sync.aligned.m8n8.x4.shared.b16 {%0,%1,%2,%3}, [%4];"
                 : "=r"(r0), "=r"(r1), "=r"(r2), "=r"(r3) : "r"(addr));
}
__device__ __forceinline__ void mma16816(float* c, const uint32_t* a, const uint32_t* b) {
    asm volatile(
        "mma.sync.aligned.m16n8k16.row.col.f32.bf16.bf16.f32 "
        "{%0,%1,%2,%3}, {%4,%5,%6,%7}, {%8,%9}, {%0,%1,%2,%3};"
        : "+f"(c[0]), "+f"(c[1]), "+f"(c[2]), "+f"(c[3])
        : "r"(a[0]), "r"(a[1]), "r"(a[2]), "r"(a[3]), "r"(b[0]), "r"(b[1]));
}
__device__ __forceinline__ float gelu_exact(float v) {
    return 0.5f * v * (1.f + erff(v * 0.70710678118654752f));
}
__device__ __forceinline__ __nv_bfloat162 split2(float v0, float v1, __nv_bfloat162& lo) {
    __nv_bfloat16 h0 = __float2bfloat16(v0), h1 = __float2bfloat16(v1);
    lo = __halves2bfloat162(__float2bfloat16(v0 - __bfloat162float(h0)),
                            __float2bfloat16(v1 - __bfloat162float(h1)));
    return __halves2bfloat162(h0, h1);
}

// ---------------- GEMM (mma.sync bf16x3 split, 4-stage pipeline) -------------
constexpr int BM = 128, BN = 128, BK = 32;
constexpr int RSB = 80;                // padded row stride in bytes (40 bf16)
constexpr int MAT_B = 128 * RSB;       // 10240 B per matrix tile
constexpr int STAGE_B = 4 * MAT_B;     // Ah, Al, Bh, Bl = 40960
constexpr int NSTAGE = 4;
constexpr int SMEM_GEMM = NSTAGE * STAGE_B; // 163840 B

// EPI: 0 = bias (fp32 out), 1 = bias+residual (fp32 out), 3 = bias+GELU -> bf16 hi/lo out
template<int EPI>
__global__ void __launch_bounds__(256, 1)
gemm_bf16x3(const __nv_bfloat16* __restrict__ Ah, const __nv_bfloat16* __restrict__ Al,
            const __nv_bfloat16* __restrict__ Bh, const __nv_bfloat16* __restrict__ Bl,
            const float* __restrict__ bias, const float* __restrict__ R,
            float* __restrict__ C,
            __nv_bfloat16* __restrict__ Ch, __nv_bfloat16* __restrict__ Cl,
            int Mr, int K, int Nc)
{
    extern __shared__ char smem[];
    const uint32_t sb = smem_to_u32(smem);
    const int tid = threadIdx.x;
    const int wid = tid >> 5, lane = tid & 31;
    const int wm = wid & 1, wn = wid >> 1;          // warp tile: (wm*64, wn*32)
    const int bm = blockIdx.y * BM, bn = blockIdx.x * BN;

    float acc[4][4][4];
    #pragma unroll
    for (int i = 0; i < 4; i++)
        #pragma unroll
        for (int j = 0; j < 4; j++)
            #pragma unroll
            for (int q = 0; q < 4; q++) acc[i][j][q] = 0.f;

    auto load_stage = [&](int stage, int k0) {
        uint32_t base = sb + stage * STAGE_B;
        #pragma unroll
        for (int i = 0; i < 2; i++) {
            int idx = tid + i*256;
            int r = idx >> 2, cb = (idx & 3) << 4;
            int gr = bm + r;
            bool v = gr < Mr;
            const char* srcH = (const char*)(Ah + (size_t)(v ? gr : 0) * K + k0) + cb;
            const char* srcL = (const char*)(Al + (size_t)(v ? gr : 0) * K + k0) + cb;
            cp_async16(base + 0*MAT_B + r*RSB + cb, srcH, v);
            cp_async16(base + 1*MAT_B + r*RSB + cb, srcL, v);
        }
        #pragma unroll
        for (int i = 0; i < 2; i++) {
            int idx = tid + i*256;
            int r = idx >> 2, cb = (idx & 3) << 4;
            const char* srcH = (const char*)(Bh + (size_t)(bn + r) * K + k0) + cb;
            const char* srcL = (const char*)(Bl + (size_t)(bn + r) * K + k0) + cb;
            cp_async16(base + 2*MAT_B + r*RSB + cb, srcH, true);
            cp_async16(base + 3*MAT_B + r*RSB + cb, srcL, true);
        }
        CP_COMMIT();
    };

    const int NC = K / BK;
    load_stage(0, 0);
    load_stage(1, BK);
    load_stage(2, 2*BK);

    // A ldmatrix lane addressing (x4: 16 rows x 16B columns)
    const int aRow = (lane & 15);
    const int aColB = (lane >> 4) * 16;
    // B combined ldmatrix x4: two 8-row n-tiles x two k-halves per instruction
    const int bMtx = lane >> 3, bRit = lane & 7;
    const int bNrow = (bMtx & 2) ? (8 + bRit) : bRit;
    const int bKoff = (bMtx & 1) * 16;

    for (int c = 0; c < NC; c++) {
        CP_WAIT(2);
        __syncthreads();
        if (c + 3 < NC) load_stage((c + 3) & 3, (c + 3) * BK);

        uint32_t st = sb + (c & 3) * STAGE_B;
        uint32_t aHb = st + 0*MAT_B, aLb = st + 1*MAT_B;
        uint32_t bHb = st + 2*MAT_B, bLb = st + 3*MAT_B;

        #pragma unroll
        for (int kk = 0; kk < 2; kk++) {
            uint32_t ah[4][4], al[4][4], bh[4][2], bl[4][2];
            #pragma unroll
            for (int mt = 0; mt < 4; mt++) {
                uint32_t off = (uint32_t)((wm*64 + mt*16 + aRow) * RSB + kk*32 + aColB);
                ldsm_x4(ah[mt][0], ah[mt][1], ah[mt][2], ah[mt][3], aHb + off);
                ldsm_x4(al[mt][0], al[mt][1], al[mt][2], al[mt][3], aLb + off);
            }
            #pragma unroll
            for (int np = 0; np < 2; np++) {
                uint32_t off = (uint32_t)((wn*32 + np*16 + bNrow) * RSB + kk*32 + bKoff);
                ldsm_x4(bh[2*np][0], bh[2*np][1], bh[2*np+1][0], bh[2*np+1][1], bHb + off);
                ldsm_x4(bl[2*np][0], bl[2*np][1], bl[2*np+1][0], bl[2*np+1][1], bLb + off);
            }
            // term-major order: same-accumulator reuse distance = 16 MMAs
            #pragma unroll
            for (int mt = 0; mt < 4; mt++)
                #pragma unroll
                for (int nt = 0; nt < 4; nt++)
                    mma16816(acc[mt][nt], ah[mt], bh[nt]);
            #pragma unroll
            for (int mt = 0; mt < 4; mt++)
                #pragma unroll
                for (int nt = 0; nt < 4; nt++)
                    mma16816(acc[mt][nt], ah[mt], bl[nt]);
            #pragma unroll
            for (int mt = 0; mt < 4; mt++)
                #pragma unroll
                for (int nt = 0; nt < 4; nt++)
                    mma16816(acc[mt][nt], al[mt], bh[nt]);
        }
    }

    const int er = lane >> 2, ec = (lane & 3) * 2;
    #pragma unroll
    for (int mt = 0; mt < 4; mt++) {
        int r0 = bm + wm*64 + mt*16 + er;
        int r1 = r0 + 8;
        #pragma unroll
        for (int nt = 0; nt < 4; nt++) {
            int cc = bn + wn*32 + nt*8 + ec;
            float b0 = bias[cc], b1 = bias[cc + 1];
            if (r0 < Mr) {
                float v0 = acc[mt][nt][0] + b0;
                float v1 = acc[mt][nt][1] + b1;
                size_t off = (size_t)r0 * Nc + cc;
                if (EPI == 1) { v0 += R[off]; v1 += R[off + 1]; }
                if (EPI == 3) {
                    v0 = gelu_exact(v0); v1 = gelu_exact(v1);
                    __nv_bfloat162 lo, hi = split2(v0, v1, lo);
                    *(__nv_bfloat162*)&Ch[off] = hi;
                    *(__nv_bfloat162*)&Cl[off] = lo;
                } else {
                    C[off] = v0; C[off + 1] = v1;
                }
            }
            if (r1 < Mr) {
                float v2 = acc[mt][nt][2] + b0;
                float v3 = acc[mt][nt][3] + b1;
                size_t off = (size_t)r1 * Nc + cc;
                if (EPI == 1) { v2 += R[off]; v3 += R[off + 1]; }
                if (EPI == 3) {
                    v2 = gelu_exact(v2); v3 = gelu_exact(v3);
                    __nv_bfloat162 lo, hi = split2(v2, v3, lo);
                    *(__nv_bfloat162*)&Ch[off] = hi;
                    *(__nv_bfloat162*)&Cl[off] = lo;
                } else {
                    C[off] = v2; C[off + 1] = v3;
                }
            }
        }
    }
}

// ---------------- LayerNorm with bf16 hi/lo split output --------------------
__global__ void ln_split_kernel(const float* __restrict__ X,
                                const float* __restrict__ gam,
                                const float* __restrict__ bet,
                                __nv_bfloat16* __restrict__ Hi,
                                __nv_bfloat16* __restrict__ Lo)
{
    int row = blockIdx.x;
    const float* x = X + (size_t)row * D;
    int tid = threadIdx.x;

    float s = 0.f, ss = 0.f;
    for (int i = tid; i < D; i += 256) { float v = x[i]; s += v; ss += v*v; }
    __shared__ float rs[32], rss[32];
    for (int o = 16; o > 0; o >>= 1) {
        s  += __shfl_xor_sync(0xffffffffu, s,  o);
        ss += __shfl_xor_sync(0xffffffffu, ss, o);
    }
    int wid = tid >> 5, lid = tid & 31;
    if (lid == 0) { rs[wid] = s; rss[wid] = ss; }
    __syncthreads();
    __shared__ float s_mean, s_inv;
    if (tid == 0) {
        float ts = 0.f, tss = 0.f;
        for (int w = 0; w < 8; w++) { ts += rs[w]; tss += rss[w]; }
        float mean = ts * (1.f/D);
        float var  = tss * (1.f/D) - mean*mean;
        s_mean = mean; s_inv = rsqrtf(var + LN_EPS);
    }
    __syncthreads();
    float mean = s_mean, inv = s_inv;
    for (int i = tid; i < D; i += 256) {
        float v = (x[i] - mean) * inv * gam[i] + bet[i];
        __nv_bfloat16 h = __float2bfloat16(v);
        Hi[(size_t)row*D + i] = h;
        Lo[(size_t)row*D + i] = __float2bfloat16(v - __bfloat162float(h));
    }
}

// ---------------- transpose + split: W[K][N] -> Th/Tl[N][K] ------------------
__global__ void tsplit_kernel(const float* __restrict__ W,
                              __nv_bfloat16* __restrict__ Th,
                              __nv_bfloat16* __restrict__ Tl, int K, int N)
{
    __shared__ float t[32][33];
    int n0 = blockIdx.x * 32, k0 = blockIdx.y * 32;
    int tx = threadIdx.x, ty = threadIdx.y;
    for (int i = ty; i < 32; i += 8)
        t[i][tx] = W[(size_t)(k0 + i) * N + n0 + tx];
    __syncthreads();
    for (int r = ty; r < 32; r += 8) {
        float v = t[tx][r];
        __nv_bfloat16 h = __float2bfloat16(v);
        size_t o = (size_t)(n0 + r) * K + k0 + tx;
        Th[o] = h;
        Tl[o] = __float2bfloat16(v - __bfloat162float(h));
    }
}

// ---------------- attention kernels (fp32 math, bf16 hi/lo output) ----------
__global__ void attn_cls_kernel(const float* __restrict__ qkv,
                                __nv_bfloat16* __restrict__ Oh,
                                __nv_bfloat16* __restrict__ Ol)
{
    int bh = blockIdx.x;
    int b = bh / H, hh = bh % H;
    int tid = threadIdx.x;

    __shared__ float qs[HD];
    __shared__ float sim[NT];
    __shared__ float red[256];
    __shared__ float red2[4][HD];

    if (tid < HD)
        qs[tid] = qkv[(size_t)(b*NT) * D3 + hh*HD + tid] * QSCALE;
    __syncthreads();

    float lmx = -1e30f;
    for (int j = tid; j < NT; j += 256) {
        const float* kp = qkv + (size_t)(b*NT + j) * D3 + D + hh*HD;
        float s = 0.f;
        #pragma unroll
        for (int d = 0; d < HD; d++) s += qs[d] * kp[d];
        sim[j] = s;
        lmx = fmaxf(lmx, s);
    }
    red[tid] = lmx; __syncthreads();
    for (int st = 128; st > 0; st >>= 1) {
        if (tid < st) red[tid] = fmaxf(red[tid], red[tid+st]);
        __syncthreads();
    }
    float mx = red[0];
    __syncthreads();

    float ls = 0.f;
    for (int j = tid; j < NT; j += 256) {
        float e = __expf(sim[j] - mx);
        sim[j] = e;
        ls += e;
    }
    red[tid] = ls; __syncthreads();
    for (int st = 128; st > 0; st >>= 1) {
        if (tid < st) red[tid] += red[tid+st];
        __syncthreads();
    }
    float linv = 1.f / red[0];
    __syncthreads();

    int d = tid & 63, p = tid >> 6;
    float acc = 0.f;
    for (int j = p; j < NT; j += 4)
        acc += sim[j] * qkv[(size_t)(b*NT + j) * D3 + 2*D + hh*HD + d];
    red2[p][d] = acc;
    __syncthreads();
    if (p == 0) {
        float o = (red2[0][d] + red2[1][d] + red2[2][d] + red2[3][d]) * linv;
        size_t idx = (size_t)(b*NT) * D + hh*HD + d;
        __nv_bfloat16 h = __float2bfloat16(o);
        Oh[idx] = h;
        Ol[idx] = __float2bfloat16(o - __bfloat162float(h));
    }
}

__global__ void attn_time_kernel(const float* __restrict__ qkv,
                                 __nv_bfloat16* __restrict__ Oh,
                                 __nv_bfloat16* __restrict__ Ol)
{
    int qid = blockIdx.x * blockDim.x + threadIdx.x;
    int fr = qid % F;
    int sp = (qid / F) % NS;
    int bh = qid / (F * NS);
    int b = bh / H, hh = bh % H;
    int t = 1 + fr*NS + sp;

    const float4* qp = (const float4*)(qkv + (size_t)(b*NT + t) * D3 + hh*HD);
    float4 q4[16];
    #pragma unroll
    for (int i = 0; i < 16; i++) {
        float4 v = qp[i];
        v.x *= QSCALE; v.y *= QSCALE; v.z *= QSCALE; v.w *= QSCALE;
        q4[i] = v;
    }

    float sim[F+1];
    #pragma unroll
    for (int j = 0; j < F+1; j++) {
        int tk = (j == 0) ? 0 : (1 + (j-1)*NS + sp);
        const float4* kp = (const float4*)(qkv + (size_t)(b*NT + tk) * D3 + D + hh*HD);
        float s = 0.f;
        #pragma unroll
        for (int i = 0; i < 16; i++) {
            float4 kk = kp[i];
            s += q4[i].x*kk.x + q4[i].y*kk.y + q4[i].z*kk.z + q4[i].w*kk.w;
        }
        sim[j] = s;
    }
    float mx = sim[0];
    #pragma unroll
    for (int j = 1; j < F+1; j++) mx = fmaxf(mx, sim[j]);
    float l = 0.f;
    #pragma unroll
    for (int j = 0; j < F+1; j++) { sim[j] = __expf(sim[j] - mx); l += sim[j]; }
    float inv = 1.f / l;

    float4 o4[16];
    #pragma unroll
    for (int i = 0; i < 16; i++) o4[i] = make_float4(0.f,0.f,0.f,0.f);
    #pragma unroll
    for (int j = 0; j < F+1; j++) {
        int tk = (j == 0) ? 0 : (1 + (j-1)*NS + sp);
        const float4* vp = (const float4*)(qkv + (size_t)(b*NT + tk) * D3 + 2*D + hh*HD);
        float p = sim[j] * inv;
        #pragma unroll
        for (int i = 0; i < 16; i++) {
            float4 vv = vp[i];
            o4[i].x += p*vv.x; o4[i].y += p*vv.y; o4[i].z += p*vv.z; o4[i].w += p*vv.w;
        }
    }
    size_t base = (size_t)(b*NT + t) * D + hh*HD;
    __nv_bfloat162* oh = (__nv_bfloat162*)&Oh[base];
    __nv_bfloat162* ol = (__nv_bfloat162*)&Ol[base];
    #pragma unroll
    for (int i = 0; i < 16; i++) {
        __nv_bfloat162 lo0, hi0 = split2(o4[i].x, o4[i].y, lo0);
        __nv_bfloat162 lo1, hi1 = split2(o4[i].z, o4[i].w, lo1);
        oh[2*i] = hi0; oh[2*i+1] = hi1;
        ol[2*i] = lo0; ol[2*i+1] = lo1;
    }
}

__global__ void attn_space_kernel(const float* __restrict__ qkv,
                                  __nv_bfloat16* __restrict__ Oh,
                                  __nv_bfloat16* __restrict__ Ol)
{
    int bx = blockIdx.x;
    int bh = bx / F, fr = bx % F;
    int b = bh / H, hh = bh % H;
    int tid = threadIdx.x;
    int sp = tid;
    const int NK = NS + 1;

    __shared__ float Ks[64 * HD];
    __shared__ float Vs[64 * HD];

    float4 q4[16], o4[16];
    float m = -1e30f, l = 0.f;
    if (sp < NS) {
        const float4* qp = (const float4*)(qkv + (size_t)(b*NT + 1 + fr*NS + sp) * D3 + hh*HD);
        #pragma unroll
        for (int i = 0; i < 16; i++) {
            float4 v = qp[i];
            v.x *= QSCALE; v.y *= QSCALE; v.z *= QSCALE; v.w *= QSCALE;
            q4[i] = v;
            o4[i] = make_float4(0.f,0.f,0.f,0.f);
        }
    }

    for (int t0 = 0; t0 < NK; t0 += 64) {
        __syncthreads();
        for (int e = tid; e < 64*HD; e += 256) {
            int jj = e >> 6, d = e & 63;
            int j = t0 + jj;
            float kv = 0.f, vv = 0.f;
            if (j < NK) {
                int tk = (j == 0) ? 0 : (1 + fr*NS + (j-1));
                size_t base = (size_t)(b*NT + tk) * D3 + hh*HD + d;
                kv = qkv[base + D];
                vv = qkv[base + 2*D];
            }
            Ks[e] = kv; Vs[e] = vv;
        }
        __syncthreads();

        if (sp < NS) {
            int lim = min(64, NK - t0);
            for (int jj = 0; jj < lim; jj++) {
                const float4* kr = (const float4*)&Ks[jj * HD];
                float s = 0.f;
                #pragma unroll
                for (int i = 0; i < 16; i++) {
                    float4 kk = kr[i];
                    s += q4[i].x*kk.x + q4[i].y*kk.y + q4[i].z*kk.z + q4[i].w*kk.w;
                }
                float mn  = fmaxf(m, s);
                float fac = __expf(m - mn);
                float p   = __expf(s - mn);
                l = l * fac + p;
                const float4* vr = (const float4*)&Vs[jj * HD];
                #pragma unroll
                for (int i = 0; i < 16; i++) {
                    float4 vv = vr[i];
                    o4[i].x = o4[i].x*fac + p*vv.x;
                    o4[i].y = o4[i].y*fac + p*vv.y;
                    o4[i].z = o4[i].z*fac + p*vv.z;
                    o4[i].w = o4[i].w*fac + p*vv.w;
                }
                m = mn;
            }
        }
    }

    if (sp < NS) {
        float inv = 1.f / l;
        size_t base = (size_t)(b*NT + 1 + fr*NS + sp) * D + hh*HD;
        __nv_bfloat162* oh = (__nv_bfloat162*)&Oh[base];
        __nv_bfloat162* ol = (__nv_bfloat162*)&Ol[base];
        #pragma unroll
        for (int i = 0; i < 16; i++) {
            __nv_bfloat162 lo0, hi0 = split2(o4[i].x*inv, o4[i].y*inv, lo0);
            __nv_bfloat162 lo1, hi1 = split2(o4[i].z*inv, o4[i].w*inv, lo1);
            oh[2*i] = hi0; oh[2*i+1] = hi1;
            ol[2*i] = lo0; ol[2*i+1] = lo1;
        }
    }
}

// ---------------- host launch ------------------------------------------------
extern "C" void kernel_launch(void* const* d_in, const int* in_sizes, int n_in,
                              void* d_out, int out_size)
{
    const float* x      = (const float*)d_in[0];
    const float* n1g    = (const float*)d_in[1];
    const float* n1b    = (const float*)d_in[2];
    const float* n2g    = (const float*)d_in[3];
    const float* n2b    = (const float*)d_in[4];
    const float* n3g    = (const float*)d_in[5];
    const float* n3b    = (const float*)d_in[6];
    const float* aqkvw  = (const float*)d_in[7];
    const float* aqkvb  = (const float*)d_in[8];
    const float* aprojw = (const float*)d_in[9];
    const float* aprojb = (const float*)d_in[10];
    const float* tqkvw  = (const float*)d_in[11];
    const float* tqkvb  = (const float*)d_in[12];
    const float* tprojw = (const float*)d_in[13];
    const float* tprojb = (const float*)d_in[14];
    const float* fc1w   = (const float*)d_in[15];
    const float* fc1b   = (const float*)d_in[16];
    const float* fc2w   = (const float*)d_in[17];
    const float* fc2b   = (const float*)d_in[18];
    float* out = (float*)d_out;

    __nv_bfloat16 *lnh, *lnl, *atth, *attl, *hidh, *hidl;
    __nv_bfloat16 *wth_tqkv, *wtl_tqkv, *wth_aqkv, *wtl_aqkv;
    __nv_bfloat16 *wth_tproj, *wtl_tproj, *wth_aproj, *wtl_aproj;
    __nv_bfloat16 *wth_fc1, *wtl_fc1, *wth_fc2, *wtl_fc2;
    float *bqkv, *btres, *bsres;
    cudaGetSymbolAddress((void**)&lnh,  g_lnh);  cudaGetSymbolAddress((void**)&lnl,  g_lnl);
    cudaGetSymbolAddress((void**)&atth, g_atth); cudaGetSymbolAddress((void**)&attl, g_attl);
    cudaGetSymbolAddress((void**)&hidh, g_hidh); cudaGetSymbolAddress((void**)&hidl, g_hidl);
    cudaGetSymbolAddress((void**)&bqkv, g_qkv);
    cudaGetSymbolAddress((void**)&btres,g_tres); cudaGetSymbolAddress((void**)&bsres,g_sres);
    cudaGetSymbolAddress((void**)&wth_tqkv, g_wth_tqkv); cudaGetSymbolAddress((void**)&wtl_tqkv, g_wtl_tqkv);
    cudaGetSymbolAddress((void**)&wth_aqkv, g_wth_aqkv); cudaGetSymbolAddress((void**)&wtl_aqkv, g_wtl_aqkv);
    cudaGetSymbolAddress((void**)&wth_tproj,g_wth_tproj);cudaGetSymbolAddress((void**)&wtl_tproj,g_wtl_tproj);
    cudaGetSymbolAddress((void**)&wth_aproj,g_wth_aproj);cudaGetSymbolAddress((void**)&wtl_aproj,g_wtl_aproj);
    cudaGetSymbolAddress((void**)&wth_fc1,  g_wth_fc1);  cudaGetSymbolAddress((void**)&wtl_fc1,  g_wtl_fc1);
    cudaGetSymbolAddress((void**)&wth_fc2,  g_wth_fc2);  cudaGetSymbolAddress((void**)&wtl_fc2,  g_wtl_fc2);

    cudaFuncSetAttribute(gemm_bf16x3<0>, cudaFuncAttributeMaxDynamicSharedMemorySize, SMEM_GEMM);
    cudaFuncSetAttribute(gemm_bf16x3<1>, cudaFuncAttributeMaxDynamicSharedMemorySize, SMEM_GEMM);
    cudaFuncSetAttribute(gemm_bf16x3<3>, cudaFuncAttributeMaxDynamicSharedMemorySize, SMEM_GEMM);

    const int MT = (M + BM - 1) / BM;    // 99
    dim3 tb(32, 8);

    // ---- weight transpose + split ----
    tsplit_kernel<<<dim3(D3/32, D/32), tb>>>(tqkvw, wth_tqkv, wtl_tqkv, D, D3);
    tsplit_kernel<<<dim3(D3/32, D/32), tb>>>(aqkvw, wth_aqkv, wtl_aqkv, D, D3);
    tsplit_kernel<<<dim3(D/32,  D/32), tb>>>(tprojw, wth_tproj, wtl_tproj, D, D);
    tsplit_kernel<<<dim3(D/32,  D/32), tb>>>(aprojw, wth_aproj, wtl_aproj, D, D);
    tsplit_kernel<<<dim3(D4/32, D/32), tb>>>(fc1w, wth_fc1, wtl_fc1, D, D4);
    tsplit_kernel<<<dim3(D/32, D4/32), tb>>>(fc2w, wth_fc2, wtl_fc2, D4, D);

    const int nTimeBlocks = (B*H*NS*F) / 256;   // 588

    // ---- time attention branch ----
    ln_split_kernel<<<M, 256>>>(x, n3g, n3b, lnh, lnl);
    gemm_bf16x3<0><<<dim3(D3/BN, MT), 256, SMEM_GEMM>>>(lnh, lnl, wth_tqkv, wtl_tqkv, tqkvb, nullptr, bqkv, nullptr, nullptr, M, D, D3);
    attn_cls_kernel <<<B*H, 256>>>(bqkv, atth, attl);
    attn_time_kernel<<<nTimeBlocks, 256>>>(bqkv, atth, attl);
    gemm_bf16x3<1><<<dim3(D/BN, MT), 256, SMEM_GEMM>>>(atth, attl, wth_tproj, wtl_tproj, tprojb, x, btres, nullptr, nullptr, M, D, D);

    // ---- space attention branch ----
    ln_split_kernel<<<M, 256>>>(btres, n1g, n1b, lnh, lnl);
    gemm_bf16x3<0><<<dim3(D3/BN, MT), 256, SMEM_GEMM>>>(lnh, lnl, wth_aqkv, wtl_aqkv, aqkvb, nullptr, bqkv, nullptr, nullptr, M, D, D3);
    attn_cls_kernel  <<<B*H, 256>>>(bqkv, atth, attl);
    attn_space_kernel<<<B*H*F, 256>>>(bqkv, atth, attl);
    gemm_bf16x3<1><<<dim3(D/BN, MT), 256, SMEM_GEMM>>>(atth, attl, wth_aproj, wtl_aproj, aprojb, x, bsres, nullptr, nullptr, M, D, D);

    // ---- MLP ----
    ln_split_kernel<<<M, 256>>>(bsres, n2g, n2b, lnh, lnl);
    gemm_bf16x3<3><<<dim3(D4/BN, MT), 256, SMEM_GEMM>>>(lnh, lnl, wth_fc1, wtl_fc1, fc1b, nullptr, nullptr, hidh, hidl, M, D, D4);
    gemm_bf16x3<1><<<dim3(D/BN, MT), 256, SMEM_GEMM>>>(hidh, hidl, wth_fc2, wtl_fc2, fc2b, bsres, out, nullptr, nullptr, M, D4, D);
}